// round 5
// baseline (speedup 1.0000x reference)
#include <cuda_runtime.h>
#include <math.h>
#include <stdint.h>

// Problem constants
#define Bn 8
#define Cn 384
#define NQ 4096
#define NK 1024
#define Hn 8
#define Dn 48
#define Fn 1536
#define GRN_EPS 1e-6f
#define LN_EPS 1e-5f

// GEMM tiling
#define KS 16
#define BM 128
#define BN 128
#define PITCHA 136  // [k][m] rows: lq*136 mod 32 = lq*8 -> conflict-free
#define PITCHR 20   // [row][k] rows: g*20 mod 32 spans all banks -> conflict-free
#define NSTAGE 3

// dynamic smem sizes (bytes)
#define CMA_AS_WORDS (NSTAGE * KS * PITCHA)
#define CMA_BS_WORDS (NSTAGE * BN * PITCHR)
#define CMA_SMEM ((CMA_AS_WORDS + CMA_BS_WORDS) * 4)
#define RMA_AS_WORDS (NSTAGE * BM * PITCHR)
#define RMA_BS_WORDS (NSTAGE * BN * PITCHR)
#define RMA_SMEM ((RMA_AS_WORDS + RMA_BS_WORDS) * 4)

// ---------------- scratch (device globals; no allocations) ----------------
__device__ float g_ada[(size_t)Bn * Cn * NQ];
__device__ float g_q[(size_t)Bn * NQ * Cn];
__device__ float g_k[(size_t)Bn * NK * Cn];
__device__ float g_v[(size_t)Bn * NK * Cn];
__device__ float g_attn[(size_t)Bn * NQ * Cn];
__device__ float g_working[(size_t)Bn * Cn * NQ];
__device__ float g_normed[(size_t)Bn * Cn * NQ];
__device__ float g_h[(size_t)Bn * NQ * Fn];
__device__ float g_kv[(size_t)Bn * Hn * Dn * Dn];
__device__ float g_ksum[(size_t)Bn * Hn * Dn];
__device__ float g_gx[(size_t)Bn * Cn];
__device__ float g_meanc[Bn];

// ---------------- helpers ----------------
__device__ __forceinline__ void cp_async16(void* smem_dst, const void* gsrc) {
    uint32_t s = (uint32_t)__cvta_generic_to_shared(smem_dst);
    asm volatile("cp.async.cg.shared.global [%0], [%1], 16;" ::"r"(s), "l"(gsrc));
}
__device__ __forceinline__ void cp_commit() { asm volatile("cp.async.commit_group;"); }
__device__ __forceinline__ void cp_wait1() { asm volatile("cp.async.wait_group 1;"); }
__device__ __forceinline__ void cp_wait0() { asm volatile("cp.async.wait_group 0;"); }

// raw fp32 bits fed as tf32 (HW truncates mantissa)
__device__ __forceinline__ void mma8(float* c, float a0, float a1, float a2, float a3,
                                     float b0, float b1) {
    asm volatile(
        "mma.sync.aligned.m16n8k8.row.col.f32.tf32.tf32.f32 "
        "{%0,%1,%2,%3},{%4,%5,%6,%7},{%8,%9},{%0,%1,%2,%3};"
        : "+f"(c[0]), "+f"(c[1]), "+f"(c[2]), "+f"(c[3])
        : "r"(__float_as_uint(a0)), "r"(__float_as_uint(a1)), "r"(__float_as_uint(a2)),
          "r"(__float_as_uint(a3)), "r"(__float_as_uint(b0)), "r"(__float_as_uint(b1)));
}

// ---------------- GRN ----------------
__global__ void grn_reduce_kernel(const float* __restrict__ x, float* __restrict__ gx, int N) {
    int bc = blockIdx.x;
    const float4* p = (const float4*)(x + (size_t)bc * N);
    int n4 = N >> 2;
    float s = 0.f;
    for (int i = threadIdx.x; i < n4; i += 256) {
        float4 v = p[i];
        s += v.x * v.x + v.y * v.y + v.z * v.z + v.w * v.w;
    }
    __shared__ float red[256];
    red[threadIdx.x] = s;
    __syncthreads();
    for (int st = 128; st > 0; st >>= 1) {
        if (threadIdx.x < st) red[threadIdx.x] += red[threadIdx.x + st];
        __syncthreads();
    }
    if (threadIdx.x == 0) gx[bc] = sqrtf(red[0]);
}

__global__ void grn_mean_kernel(const float* __restrict__ gx, float* __restrict__ meanc) {
    int b = blockIdx.x;
    int t = threadIdx.x;  // 128
    float s = 0.f;
    for (int c = t; c < Cn; c += 128) s += gx[b * Cn + c];
    __shared__ float red[128];
    red[t] = s;
    __syncthreads();
    for (int st = 64; st > 0; st >>= 1) {
        if (t < st) red[t] += red[t + st];
        __syncthreads();
    }
    if (t == 0) meanc[b] = red[0] * (1.f / (float)Cn) + GRN_EPS;
}

__global__ void grn_apply_kernel(const float* __restrict__ x, const float* __restrict__ gx,
                                 const float* __restrict__ meanc,
                                 const float* __restrict__ gamma, const float* __restrict__ beta,
                                 float* __restrict__ out) {
    const int N4 = NQ >> 2;  // 1024
    size_t total = (size_t)Bn * Cn * N4;
    size_t stride = (size_t)gridDim.x * blockDim.x;
    const float4* x4 = (const float4*)x;
    float4* o4 = (float4*)out;
    for (size_t i = (size_t)blockIdx.x * blockDim.x + threadIdx.x; i < total; i += stride) {
        size_t bc = i >> 10;
        int c = (int)(bc % Cn);
        int b = (int)(bc / Cn);
        float nx = gx[bc] / meanc[b];
        float sc = 1.f + (1.f + gamma[c]) * nx;
        float bt = beta[c];
        float4 v = x4[i];
        o4[i] = make_float4(v.x * sc + bt, v.y * sc + bt, v.z * sc + bt, v.w * sc + bt);
    }
}

// ---------------- tensor-core GEMM: channel-major A, 3-stage cp.async, 1 sync/slab ----
// Y[b,m,co] = sum_k X[b,k,m] * W[co,k] + bias[co];  act 1 = silu
__global__ __launch_bounds__(256) void gemm_cmA_tc(
    const float* __restrict__ X, const float* __restrict__ W,
    const float* __restrict__ bias, float* __restrict__ Y,
    int N, int Cin, int Cout, int act) {
    extern __shared__ float sm[];
    float* As = sm;                 // [stage][k][PITCHA]
    float* Bs = sm + CMA_AS_WORDS;  // [stage][co][PITCHR]
    int b = blockIdx.z;
    int m0 = blockIdx.x * BM;
    int c0 = blockIdx.y * BN;
    int tid = threadIdx.x;
    int warp = tid >> 5, lane = tid & 31;
    int g = lane >> 2, lq = lane & 3;
    int wm = (warp >> 2) * 64;
    int wn = (warp & 3) * 32;
    float acc[4][4][4] = {};
    const float* Xb = X + (size_t)b * Cin * N;
    int nslab = Cin / KS;

#define LOAD_CM(slab, stg)                                                               \
    {                                                                                    \
        int kk0 = (slab)*KS;                                                             \
        float* Ad = As + (size_t)(stg)*KS * PITCHA;                                      \
        float* Bd = Bs + (size_t)(stg)*BN * PITCHR;                                      \
        _Pragma("unroll") for (int p = 0; p < 2; p++) {                                  \
            int c = tid + p * 256;                                                       \
            int ak = c >> 5, am = (c & 31) << 2;                                         \
            cp_async16(Ad + ak * PITCHA + am, Xb + (size_t)(kk0 + ak) * N + m0 + am);    \
            int bc = c >> 2, bk = (c & 3) << 2;                                          \
            cp_async16(Bd + bc * PITCHR + bk, W + (size_t)(c0 + bc) * Cin + kk0 + bk);   \
        }                                                                                \
        cp_commit();                                                                     \
    }

    LOAD_CM(0, 0);
    LOAD_CM(1, 1);
    for (int s = 0; s < nslab; s++) {
        int stg = s % NSTAGE;
        // wait: FIFO groups -> leaving <=1 pending means group s is done (the pending
        // one, if any, is s+1). Last iteration must drain fully.
        if (s + 1 < nslab) cp_wait1(); else cp_wait0();
        __syncthreads();  // all warps finished compute of slab s-1 -> stage (s-1)%3 free
        if (s + 2 < nslab) LOAD_CM(s + 2, (s + 2) % NSTAGE);  // writes stage (s-1)%3: safe
        const float* Ac = As + (size_t)stg * KS * PITCHA;
        const float* Bc = Bs + (size_t)stg * BN * PITCHR;
#pragma unroll
        for (int ks = 0; ks < KS; ks += 8) {
            float af[4][4], bf[4][2];
#pragma unroll
            for (int mf = 0; mf < 4; mf++) {
                int m = wm + mf * 16 + g;
                af[mf][0] = Ac[(ks + lq) * PITCHA + m];
                af[mf][1] = Ac[(ks + lq) * PITCHA + m + 8];
                af[mf][2] = Ac[(ks + lq + 4) * PITCHA + m];
                af[mf][3] = Ac[(ks + lq + 4) * PITCHA + m + 8];
            }
#pragma unroll
            for (int nf = 0; nf < 4; nf++) {
                int c = wn + nf * 8 + g;
                bf[nf][0] = Bc[c * PITCHR + ks + lq];
                bf[nf][1] = Bc[c * PITCHR + ks + lq + 4];
            }
#pragma unroll
            for (int mf = 0; mf < 4; mf++)
#pragma unroll
                for (int nf = 0; nf < 4; nf++)
                    mma8(acc[mf][nf], af[mf][0], af[mf][1], af[mf][2], af[mf][3],
                         bf[nf][0], bf[nf][1]);
        }
    }
#undef LOAD_CM

    float* Yb = Y + (size_t)b * N * Cout;
#pragma unroll
    for (int mf = 0; mf < 4; mf++) {
#pragma unroll
        for (int nf = 0; nf < 4; nf++) {
            int co = c0 + wn + nf * 8 + lq * 2;
            float b0v = bias[co], b1v = bias[co + 1];
#pragma unroll
            for (int hr = 0; hr < 2; hr++) {
                int m = m0 + wm + mf * 16 + g + hr * 8;
                float v0 = acc[mf][nf][hr * 2 + 0] + b0v;
                float v1 = acc[mf][nf][hr * 2 + 1] + b1v;
                if (act == 1) {
                    v0 = v0 / (1.f + expf(-v0));
                    v1 = v1 / (1.f + expf(-v1));
                }
                *(float2*)(Yb + (size_t)m * Cout + co) = make_float2(v0, v1);
            }
        }
    }
}

// ---------------- tensor-core GEMM: row-major A, channel-major fused out ----------------
// val[b,m,co] = sum_k X[b,m,k]*W[co,k] + bias[co]
// mode 0: out[b,co,m] = resid1 + val*s1[co]
// mode 1: out[b,co,m] = resid1 + (resid2 + val*s1[co]) * s2[co]
__global__ __launch_bounds__(256) void gemm_rmA_tc(
    const float* __restrict__ X, const float* __restrict__ W,
    const float* __restrict__ bias,
    const float* __restrict__ resid1, const float* __restrict__ resid2,
    const float* __restrict__ scal1, const float* __restrict__ scal2,
    float* __restrict__ out, int N, int F, int Cout, int mode) {
    extern __shared__ float sm[];
    float* As = sm;                 // [stage][m][PITCHR]
    float* Bs = sm + RMA_AS_WORDS;  // [stage][co][PITCHR]
    int b = blockIdx.z;
    int m0 = blockIdx.x * BM;
    int c0 = blockIdx.y * BN;
    int tid = threadIdx.x;
    int warp = tid >> 5, lane = tid & 31;
    int g = lane >> 2, lq = lane & 3;
    int wm = (warp >> 2) * 64;
    int wn = (warp & 3) * 32;
    float acc[4][4][4] = {};
    const float* Xb = X + (size_t)b * N * F;
    int nslab = F / KS;

#define LOAD_RM(slab, stg)                                                              \
    {                                                                                   \
        int kk0 = (slab)*KS;                                                            \
        float* Ad = As + (size_t)(stg)*BM * PITCHR;                                     \
        float* Bd = Bs + (size_t)(stg)*BN * PITCHR;                                     \
        _Pragma("unroll") for (int p = 0; p < 2; p++) {                                 \
            int c = tid + p * 256;                                                      \
            int r = c >> 2, kk = (c & 3) << 2;                                          \
            cp_async16(Ad + r * PITCHR + kk, Xb + (size_t)(m0 + r) * F + kk0 + kk);     \
            cp_async16(Bd + r * PITCHR + kk, W + (size_t)(c0 + r) * F + kk0 + kk);      \
        }                                                                               \
        cp_commit();                                                                    \
    }

    LOAD_RM(0, 0);
    LOAD_RM(1, 1);
    for (int s = 0; s < nslab; s++) {
        int stg = s % NSTAGE;
        if (s + 1 < nslab) cp_wait1(); else cp_wait0();
        __syncthreads();
        if (s + 2 < nslab) LOAD_RM(s + 2, (s + 2) % NSTAGE);
        const float* Ac = As + (size_t)stg * BM * PITCHR;
        const float* Bc = Bs + (size_t)stg * BN * PITCHR;
#pragma unroll
        for (int ks = 0; ks < KS; ks += 8) {
            float af[4][4], bf[4][2];
#pragma unroll
            for (int mf = 0; mf < 4; mf++) {
                int m = wm + mf * 16 + g;
                af[mf][0] = Ac[m * PITCHR + ks + lq];
                af[mf][1] = Ac[(m + 8) * PITCHR + ks + lq];
                af[mf][2] = Ac[m * PITCHR + ks + lq + 4];
                af[mf][3] = Ac[(m + 8) * PITCHR + ks + lq + 4];
            }
#pragma unroll
            for (int nf = 0; nf < 4; nf++) {
                int c = wn + nf * 8 + g;
                bf[nf][0] = Bc[c * PITCHR + ks + lq];
                bf[nf][1] = Bc[c * PITCHR + ks + lq + 4];
            }
#pragma unroll
            for (int mf = 0; mf < 4; mf++)
#pragma unroll
                for (int nf = 0; nf < 4; nf++)
                    mma8(acc[mf][nf], af[mf][0], af[mf][1], af[mf][2], af[mf][3],
                         bf[nf][0], bf[nf][1]);
        }
    }
#undef LOAD_RM

#pragma unroll
    for (int nf = 0; nf < 4; nf++) {
#pragma unroll
        for (int cj = 0; cj < 2; cj++) {
            int co = c0 + wn + nf * 8 + lq * 2 + cj;
            float bv = bias[co];
            float s1 = scal1[co];
            float s2 = (mode == 1) ? scal2[co] : 0.f;
#pragma unroll
            for (int mf = 0; mf < 4; mf++) {
#pragma unroll
                for (int hr = 0; hr < 2; hr++) {
                    int m = m0 + wm + mf * 16 + g + hr * 8;
                    size_t idx = ((size_t)b * Cout + co) * (size_t)N + m;
                    float val = acc[mf][nf][hr * 2 + cj] + bv;
                    if (mode == 0)
                        out[idx] = resid1[idx] + val * s1;
                    else
                        out[idx] = resid1[idx] + (resid2[idx] + val * s1) * s2;
                }
            }
        }
    }
}

// ---------------- LayerNorm + elu+1 (in place on (rows, C)) ----------------
__global__ void ln_elu_kernel(float* __restrict__ x, const float* __restrict__ w,
                              const float* __restrict__ bvec) {
    int r = blockIdx.x;
    float* p = x + (size_t)r * Cn;
    int t = threadIdx.x;  // 128
    float v0 = p[t], v1 = p[t + 128], v2 = p[t + 256];
    float s = v0 + v1 + v2;
    float s2 = v0 * v0 + v1 * v1 + v2 * v2;
    __shared__ float red[128];
    red[t] = s;
    __syncthreads();
    for (int st = 64; st > 0; st >>= 1) {
        if (t < st) red[t] += red[t + st];
        __syncthreads();
    }
    float mu = red[0] * (1.f / (float)Cn);
    __syncthreads();
    red[t] = s2;
    __syncthreads();
    for (int st = 64; st > 0; st >>= 1) {
        if (t < st) red[t] += red[t + st];
        __syncthreads();
    }
    float var = red[0] * (1.f / (float)Cn) - mu * mu;
    float inv = rsqrtf(var + LN_EPS);
    float y;
    y = (v0 - mu) * inv * w[t] + bvec[t];
    p[t] = (y > 0.f) ? y + 1.f : expf(y);
    y = (v1 - mu) * inv * w[t + 128] + bvec[t + 128];
    p[t + 128] = (y > 0.f) ? y + 1.f : expf(y);
    y = (v2 - mu) * inv * w[t + 256] + bvec[t + 256];
    p[t + 256] = (y > 0.f) ? y + 1.f : expf(y);
}

// ---------------- kv_sum + k_sum per (b,h) ----------------
__global__ void kv_kernel(const float* __restrict__ k, const float* __restrict__ v,
                          float* __restrict__ kv, float* __restrict__ ksum) {
    int bh = blockIdx.x;
    int b = bh / Hn, h = bh % Hn;
    __shared__ float ks[32][Dn];
    __shared__ float vs[32][Dn];
    int tid = threadIdx.x;  // 256
    float acc[9] = {};
    float ksacc = 0.f;
    for (int n0 = 0; n0 < NK; n0 += 32) {
        for (int i = tid; i < 32 * Dn; i += 256) {
            int nn = i / Dn, dd = i % Dn;
            size_t base = ((size_t)b * NK + n0 + nn) * Cn + h * Dn + dd;
            ks[nn][dd] = k[base];
            vs[nn][dd] = v[base];
        }
        __syncthreads();
#pragma unroll 4
        for (int nn = 0; nn < 32; nn++) {
#pragma unroll
            for (int o = 0; o < 9; o++) {
                int idx = tid + o * 256;
                int dd = idx / Dn, ee = idx % Dn;
                acc[o] += ks[nn][dd] * vs[nn][ee];
            }
            if (tid < Dn) ksacc += ks[nn][tid];
        }
        __syncthreads();
    }
#pragma unroll
    for (int o = 0; o < 9; o++) kv[(size_t)bh * Dn * Dn + tid + o * 256] = acc[o];
    if (tid < Dn) ksum[bh * Dn + tid] = ksacc;
}

// ---------------- attention: num/den ----------------
__global__ void attn_kernel(const float* __restrict__ q, const float* __restrict__ kv,
                            const float* __restrict__ ksum, float* __restrict__ attn) {
    int bh = blockIdx.y;
    int b = bh / Hn, h = bh % Hn;
    int n0 = blockIdx.x * 64;
    __shared__ float kvs[Dn][Dn];
    __shared__ float kss[Dn];
    __shared__ float qs[64][Dn];
    __shared__ float dens[64];
    int tid = threadIdx.x;  // 256
    for (int i = tid; i < Dn * Dn; i += 256) kvs[i / Dn][i % Dn] = kv[(size_t)bh * Dn * Dn + i];
    if (tid < Dn) kss[tid] = ksum[bh * Dn + tid];
    for (int i = tid; i < 64 * Dn; i += 256) {
        int nn = i / Dn, dd = i % Dn;
        qs[nn][dd] = q[((size_t)b * NQ + n0 + nn) * Cn + h * Dn + dd];
    }
    __syncthreads();
    if (tid < 64) {
        float den = 0.f;
#pragma unroll
        for (int dd = 0; dd < Dn; dd++) den += qs[tid][dd] * kss[dd];
        dens[tid] = den + 1e-8f;
    }
    __syncthreads();
#pragma unroll
    for (int o = 0; o < 12; o++) {
        int idx = tid + o * 256;
        int nn = idx / Dn, ee = idx % Dn;
        float sacc = 0.f;
#pragma unroll
        for (int dd = 0; dd < Dn; dd++) sacc += qs[nn][dd] * kvs[dd][ee];
        attn[((size_t)b * NQ + n0 + nn) * Cn + h * Dn + ee] = sacc / dens[nn];
    }
}

// ---------------- host launch ----------------
extern "C" void kernel_launch(void* const* d_in, const int* in_sizes, int n_in,
                              void* d_out, int out_size) {
    const float* query = (const float*)d_in[0];
    const float* key = (const float*)d_in[1];
    const float* value = (const float*)d_in[2];
    const float* ada_gamma = (const float*)d_in[3];
    const float* ada_beta = (const float*)d_in[4];
    const float* Wq = (const float*)d_in[5];
    const float* bq = (const float*)d_in[6];
    const float* Wk = (const float*)d_in[7];
    const float* bk = (const float*)d_in[8];
    const float* Wv = (const float*)d_in[9];
    const float* bv = (const float*)d_in[10];
    const float* Wo = (const float*)d_in[11];
    const float* bo = (const float*)d_in[12];
    const float* lnq_w = (const float*)d_in[13];
    const float* lnq_b = (const float*)d_in[14];
    const float* lnk_w = (const float*)d_in[15];
    const float* lnk_b = (const float*)d_in[16];
    const float* attn_scalar = (const float*)d_in[17];
    const float* ffn_gamma = (const float*)d_in[18];
    const float* ffn_beta = (const float*)d_in[19];
    const float* W1 = (const float*)d_in[20];
    const float* b1 = (const float*)d_in[21];
    const float* W2 = (const float*)d_in[22];
    const float* b2 = (const float*)d_in[23];
    const float* ffn_scalar = (const float*)d_in[24];
    const float* final_scalar = (const float*)d_in[25];
    float* out = (float*)d_out;

    float *ada, *q, *k, *v, *attn, *working, *normed, *hbuf, *kv, *ksum, *gx, *meanc;
    cudaGetSymbolAddress((void**)&ada, g_ada);
    cudaGetSymbolAddress((void**)&q, g_q);
    cudaGetSymbolAddress((void**)&k, g_k);
    cudaGetSymbolAddress((void**)&v, g_v);
    cudaGetSymbolAddress((void**)&attn, g_attn);
    cudaGetSymbolAddress((void**)&working, g_working);
    cudaGetSymbolAddress((void**)&normed, g_normed);
    cudaGetSymbolAddress((void**)&hbuf, g_h);
    cudaGetSymbolAddress((void**)&kv, g_kv);
    cudaGetSymbolAddress((void**)&ksum, g_ksum);
    cudaGetSymbolAddress((void**)&gx, g_gx);
    cudaGetSymbolAddress((void**)&meanc, g_meanc);

    cudaFuncSetAttribute(gemm_cmA_tc, cudaFuncAttributeMaxDynamicSharedMemorySize, CMA_SMEM);
    cudaFuncSetAttribute(gemm_rmA_tc, cudaFuncAttributeMaxDynamicSharedMemorySize, RMA_SMEM);

    // 1) GRN on query -> ada
    grn_reduce_kernel<<<Bn * Cn, 256>>>(query, gx, NQ);
    grn_mean_kernel<<<Bn, 128>>>(gx, meanc);
    grn_apply_kernel<<<2048, 256>>>(query, gx, meanc, ada_gamma, ada_beta, ada);

    // 2) projections
    gemm_cmA_tc<<<dim3(NQ / BM, Cn / BN, Bn), 256, CMA_SMEM>>>(ada, Wq, bq, q, NQ, Cn, Cn, 0);
    gemm_cmA_tc<<<dim3(NK / BM, Cn / BN, Bn), 256, CMA_SMEM>>>(key, Wk, bk, k, NK, Cn, Cn, 0);
    gemm_cmA_tc<<<dim3(NK / BM, Cn / BN, Bn), 256, CMA_SMEM>>>(value, Wv, bv, v, NK, Cn, Cn, 0);

    // 3) LN + elu+1 (in place)
    ln_elu_kernel<<<Bn * NQ, 128>>>(q, lnq_w, lnq_b);
    ln_elu_kernel<<<Bn * NK, 128>>>(k, lnk_w, lnk_b);

    // 4) kv_sum, k_sum
    kv_kernel<<<Bn * Hn, 256>>>(k, v, kv, ksum);

    // 5) linear attention num/den
    attn_kernel<<<dim3(NQ / 64, Bn * Hn), 256>>>(q, kv, ksum, attn);

    // 6) Wo projection + attn residual -> working (channel-major)
    gemm_rmA_tc<<<dim3(NQ / BM, Cn / BN, Bn), 256, RMA_SMEM>>>(
        attn, Wo, bo, query, nullptr, attn_scalar, nullptr, working, NQ, Cn, Cn, 0);

    // 7) GRN on working -> normed
    grn_reduce_kernel<<<Bn * Cn, 256>>>(working, gx, NQ);
    grn_mean_kernel<<<Bn, 128>>>(gx, meanc);
    grn_apply_kernel<<<2048, 256>>>(working, gx, meanc, ffn_gamma, ffn_beta, normed);

    // 8) FFN1 (+silu) -> h
    gemm_cmA_tc<<<dim3(NQ / BM, Fn / BN, Bn), 256, CMA_SMEM>>>(normed, W1, b1, hbuf, NQ, Cn, Fn, 1);

    // 9) FFN2 + ffn residual + final residual -> out
    gemm_rmA_tc<<<dim3(NQ / BM, Cn / BN, Bn), 256, RMA_SMEM>>>(
        hbuf, W2, b2, query, working, ffn_scalar, final_scalar, out, NQ, Fn, Cn, 1);
}

// round 6
// speedup vs baseline: 1.2427x; 1.2427x over previous
#include <cuda_runtime.h>
#include <cuda_bf16.h>
#include <math.h>
#include <stdint.h>

// Problem constants
#define Bn 8
#define Cn 384
#define NQ 4096
#define NK 1024
#define Hn 8
#define Dn 48
#define Fn 1536
#define GRN_EPS 1e-6f
#define LN_EPS 1e-5f

// GEMM tiling (bf16)
#define BM 128
#define BN 128
#define KSB 32        // k elements per slab
#define KW 16         // uint32 words per row (KSB/2)
#define NSTAGE 3
#define GW (BM * KW)  // words per stage per operand (2048)
#define GEMM_SMEM (NSTAGE * 2 * GW * 4)  // 49152 bytes

#define CC (Cn * Cn)
#define FC (Fn * Cn)

// ---------------- scratch (device globals; no allocations) ----------------
__device__ float g_q[(size_t)Bn * NQ * Cn];
__device__ float g_k[(size_t)Bn * NK * Cn];
__device__ float g_v[(size_t)Bn * NK * Cn];
__device__ float g_working[(size_t)Bn * Cn * NQ];
__device__ float g_kv[(size_t)Bn * Hn * Dn * Dn];
__device__ float g_ksum[(size_t)Bn * Hn * Dn];
__device__ float g_gx[(size_t)Bn * Cn];
__device__ float g_meanc[Bn];

__device__ __nv_bfloat16 b_ada[(size_t)Bn * NQ * Cn];
__device__ __nv_bfloat16 b_key[(size_t)Bn * NK * Cn];
__device__ __nv_bfloat16 b_val[(size_t)Bn * NK * Cn];
__device__ __nv_bfloat16 b_attn[(size_t)Bn * NQ * Cn];
__device__ __nv_bfloat16 b_nrm[(size_t)Bn * NQ * Cn];
__device__ __nv_bfloat16 b_h[(size_t)Bn * NQ * Fn];
__device__ __nv_bfloat16 b_wts[4 * CC + 2 * FC];

// ---------------- helpers ----------------
__device__ __forceinline__ void cp_async16(void* smem_dst, const void* gsrc) {
    uint32_t s = (uint32_t)__cvta_generic_to_shared(smem_dst);
    asm volatile("cp.async.cg.shared.global [%0], [%1], 16;" ::"r"(s), "l"(gsrc));
}
__device__ __forceinline__ void cp_commit() { asm volatile("cp.async.commit_group;"); }
__device__ __forceinline__ void cp_wait1() { asm volatile("cp.async.wait_group 1;"); }
__device__ __forceinline__ void cp_wait0() { asm volatile("cp.async.wait_group 0;"); }

__device__ __forceinline__ void mma16(float* c, uint32_t a0, uint32_t a1, uint32_t a2,
                                      uint32_t a3, uint32_t b0, uint32_t b1) {
    asm volatile(
        "mma.sync.aligned.m16n8k16.row.col.f32.bf16.bf16.f32 "
        "{%0,%1,%2,%3},{%4,%5,%6,%7},{%8,%9},{%0,%1,%2,%3};"
        : "+f"(c[0]), "+f"(c[1]), "+f"(c[2]), "+f"(c[3])
        : "r"(a0), "r"(a1), "r"(a2), "r"(a3), "r"(b0), "r"(b1));
}

// swizzled read: logical word w (0..15) of row
__device__ __forceinline__ uint32_t lds_sw(const uint32_t* base, int row, int w) {
    return base[row * KW + ((((w >> 2) ^ ((row >> 1) & 3)) << 2) | (w & 3))];
}

// ---------------- weight/elementwise convert ----------------
__global__ void conv_f2bf(const float4* __restrict__ src, __nv_bfloat162* __restrict__ dst,
                          int n4) {
    int i = blockIdx.x * 256 + threadIdx.x;
    if (i < n4) {
        float4 v = src[i];
        __nv_bfloat162 a, b;
        a.x = __float2bfloat16_rn(v.x); a.y = __float2bfloat16_rn(v.y);
        b.x = __float2bfloat16_rn(v.z); b.y = __float2bfloat16_rn(v.w);
        dst[2 * i] = a;
        dst[2 * i + 1] = b;
    }
}

// ---------------- GRN ----------------
__global__ void grn_reduce_kernel(const float* __restrict__ x, float* __restrict__ gx, int N) {
    int bc = blockIdx.x;
    const float4* p = (const float4*)(x + (size_t)bc * N);
    int n4 = N >> 2;
    float s = 0.f;
    for (int i = threadIdx.x; i < n4; i += 256) {
        float4 v = p[i];
        s += v.x * v.x + v.y * v.y + v.z * v.z + v.w * v.w;
    }
    __shared__ float red[256];
    red[threadIdx.x] = s;
    __syncthreads();
    for (int st = 128; st > 0; st >>= 1) {
        if (threadIdx.x < st) red[threadIdx.x] += red[threadIdx.x + st];
        __syncthreads();
    }
    if (threadIdx.x == 0) gx[bc] = sqrtf(red[0]);
}

__global__ void grn_mean_kernel(const float* __restrict__ gx, float* __restrict__ meanc) {
    int b = blockIdx.x;
    int t = threadIdx.x;  // 128
    float s = 0.f;
    for (int c = t; c < Cn; c += 128) s += gx[b * Cn + c];
    __shared__ float red[128];
    red[t] = s;
    __syncthreads();
    for (int st = 64; st > 0; st >>= 1) {
        if (t < st) red[t] += red[t + st];
        __syncthreads();
    }
    if (t == 0) meanc[b] = red[0] * (1.f / (float)Cn) + GRN_EPS;
}

// ---------------- transpose + (optional GRN) + convert to bf16 rows ----------------
// in: x [b][c][n] fp32; out: [b][n][c] bf16 with out = x*sc[c] + bt[c]
// grn: sc = 1 + (1+gamma)*gx/meanc, bt = beta ; else sc=1, bt=0
__global__ void transconv_kernel(const float* __restrict__ x, __nv_bfloat16* __restrict__ out,
                                 const float* __restrict__ gx, const float* __restrict__ meanc,
                                 const float* __restrict__ gamma, const float* __restrict__ beta,
                                 int N, int grn) {
    int b = blockIdx.z;
    int c0 = blockIdx.x * 64;
    int n0 = blockIdx.y * 32;
    __shared__ float t[64][33];
    int tid = threadIdx.x;
    int j = tid & 31, i0 = tid >> 5;
#pragma unroll
    for (int p = 0; p < 8; p++) {
        int i = i0 + p * 8;
        t[i][j] = x[((size_t)b * Cn + c0 + i) * N + n0 + j];
    }
    __syncthreads();
    int cp = tid & 31;        // c pair index
    int nn0 = tid >> 5;       // n base
    int c = c0 + 2 * cp;
    float sc0 = 1.f, bt0 = 0.f, sc1 = 1.f, bt1 = 0.f;
    if (grn) {
        sc0 = 1.f + (1.f + gamma[c]) * gx[b * Cn + c] / meanc[b];
        bt0 = beta[c];
        sc1 = 1.f + (1.f + gamma[c + 1]) * gx[b * Cn + c + 1] / meanc[b];
        bt1 = beta[c + 1];
    }
#pragma unroll
    for (int p = 0; p < 4; p++) {
        int nn = nn0 + p * 8;
        float v0 = t[2 * cp][nn] * sc0 + bt0;
        float v1 = t[2 * cp + 1][nn] * sc1 + bt1;
        __nv_bfloat162 hv;
        hv.x = __float2bfloat16_rn(v0);
        hv.y = __float2bfloat16_rn(v1);
        *(__nv_bfloat162*)(out + ((size_t)b * N + n0 + nn) * Cn + c) = hv;
    }
}

// ---------------- bf16 GEMM, row-major output ----------------
// Y[b,m,co] = sum_k A[b,m,k]*W[co,k] + bias[co]
// mode 0: Yf fp32, no act.  mode 1: Yh bf16, silu.
__global__ __launch_bounds__(256) void gemm_bf16_row(
    const __nv_bfloat16* __restrict__ A, const __nv_bfloat16* __restrict__ W,
    const float* __restrict__ bias, float* __restrict__ Yf, __nv_bfloat16* __restrict__ Yh,
    int N, int K, int Cout, int mode) {
    extern __shared__ uint32_t smu[];
    uint32_t* As = smu;
    uint32_t* Bs = smu + NSTAGE * GW;
    int b = blockIdx.z;
    int m0 = blockIdx.x * BM;
    int c0 = blockIdx.y * BN;
    int tid = threadIdx.x;
    int warp = tid >> 5, lane = tid & 31;
    int g = lane >> 2, lq = lane & 3;
    int wm = (warp >> 2) * 64;
    int wn = (warp & 3) * 32;
    float acc[4][4][4] = {};
    const __nv_bfloat16* Ab = A + (size_t)b * N * K;
    int nslab = K / KSB;

#define LOAD_BF(slab, stg)                                                              \
    {                                                                                   \
        int kk0 = (slab)*KSB;                                                           \
        uint32_t* Ad = As + (size_t)(stg)*GW;                                           \
        uint32_t* Bd = Bs + (size_t)(stg)*GW;                                           \
        _Pragma("unroll") for (int p = 0; p < 2; p++) {                                 \
            int c = tid + p * 256;                                                      \
            int r = c >> 2, ch = c & 3;                                                 \
            int sw = ((ch ^ ((r >> 1) & 3)) << 2);                                      \
            cp_async16(Ad + r * KW + sw, Ab + (size_t)(m0 + r) * K + kk0 + ch * 8);     \
            cp_async16(Bd + r * KW + sw, W + (size_t)(c0 + r) * K + kk0 + ch * 8);      \
        }                                                                               \
        cp_commit();                                                                    \
    }

    LOAD_BF(0, 0);
    LOAD_BF(1, 1);
    for (int s = 0; s < nslab; s++) {
        int stg = s % NSTAGE;
        if (s + 1 < nslab) cp_wait1(); else cp_wait0();
        __syncthreads();
        if (s + 2 < nslab) LOAD_BF(s + 2, (s + 2) % NSTAGE);
        const uint32_t* Ac = As + (size_t)stg * GW;
        const uint32_t* Bc = Bs + (size_t)stg * GW;
#pragma unroll
        for (int kb = 0; kb < 2; kb++) {
            int wb = kb * 8;
            uint32_t af[4][4], bfr[4][2];
#pragma unroll
            for (int mf = 0; mf < 4; mf++) {
                int m = wm + mf * 16 + g;
                af[mf][0] = lds_sw(Ac, m, wb + lq);
                af[mf][1] = lds_sw(Ac, m + 8, wb + lq);
                af[mf][2] = lds_sw(Ac, m, wb + lq + 4);
                af[mf][3] = lds_sw(Ac, m + 8, wb + lq + 4);
            }
#pragma unroll
            for (int nf = 0; nf < 4; nf++) {
                int cc = wn + nf * 8 + g;
                bfr[nf][0] = lds_sw(Bc, cc, wb + lq);
                bfr[nf][1] = lds_sw(Bc, cc, wb + lq + 4);
            }
#pragma unroll
            for (int mf = 0; mf < 4; mf++)
#pragma unroll
                for (int nf = 0; nf < 4; nf++)
                    mma16(acc[mf][nf], af[mf][0], af[mf][1], af[mf][2], af[mf][3],
                          bfr[nf][0], bfr[nf][1]);
        }
    }
#undef LOAD_BF

#pragma unroll
    for (int mf = 0; mf < 4; mf++) {
#pragma unroll
        for (int nf = 0; nf < 4; nf++) {
            int co = c0 + wn + nf * 8 + lq * 2;
            float b0v = bias[co], b1v = bias[co + 1];
#pragma unroll
            for (int hr = 0; hr < 2; hr++) {
                int m = m0 + wm + mf * 16 + g + hr * 8;
                float v0 = acc[mf][nf][hr * 2 + 0] + b0v;
                float v1 = acc[mf][nf][hr * 2 + 1] + b1v;
                if (mode == 1) {
                    v0 = v0 / (1.f + expf(-v0));
                    v1 = v1 / (1.f + expf(-v1));
                    __nv_bfloat162 hv;
                    hv.x = __float2bfloat16_rn(v0);
                    hv.y = __float2bfloat16_rn(v1);
                    *(__nv_bfloat162*)(Yh + ((size_t)b * N + m) * Cout + co) = hv;
                } else {
                    *(float2*)(Yf + ((size_t)b * N + m) * Cout + co) = make_float2(v0, v1);
                }
            }
        }
    }
}

// ---------------- bf16 GEMM, channel-major fused output ----------------
// val = sum_k A[b,m,k]*W[co,k] + bias[co]
// mode 0: out[b,co,m] = resid1 + val*s1[co]
// mode 1: out[b,co,m] = resid1 + (resid2 + val*s1[co]) * s2[co]
__global__ __launch_bounds__(256) void gemm_bf16_cm(
    const __nv_bfloat16* __restrict__ A, const __nv_bfloat16* __restrict__ W,
    const float* __restrict__ bias,
    const float* __restrict__ resid1, const float* __restrict__ resid2,
    const float* __restrict__ scal1, const float* __restrict__ scal2,
    float* __restrict__ out, int N, int K, int Cout, int mode) {
    extern __shared__ uint32_t smu[];
    uint32_t* As = smu;
    uint32_t* Bs = smu + NSTAGE * GW;
    int b = blockIdx.z;
    int m0 = blockIdx.x * BM;
    int c0 = blockIdx.y * BN;
    int tid = threadIdx.x;
    int warp = tid >> 5, lane = tid & 31;
    int g = lane >> 2, lq = lane & 3;
    int wm = (warp >> 2) * 64;
    int wn = (warp & 3) * 32;
    float acc[4][4][4] = {};
    const __nv_bfloat16* Ab = A + (size_t)b * N * K;
    int nslab = K / KSB;

#define LOAD_BF(slab, stg)                                                              \
    {                                                                                   \
        int kk0 = (slab)*KSB;                                                           \
        uint32_t* Ad = As + (size_t)(stg)*GW;                                           \
        uint32_t* Bd = Bs + (size_t)(stg)*GW;                                           \
        _Pragma("unroll") for (int p = 0; p < 2; p++) {                                 \
            int c = tid + p * 256;                                                      \
            int r = c >> 2, ch = c & 3;                                                 \
            int sw = ((ch ^ ((r >> 1) & 3)) << 2);                                      \
            cp_async16(Ad + r * KW + sw, Ab + (size_t)(m0 + r) * K + kk0 + ch * 8);     \
            cp_async16(Bd + r * KW + sw, W + (size_t)(c0 + r) * K + kk0 + ch * 8);      \
        }                                                                               \
        cp_commit();                                                                    \
    }

    LOAD_BF(0, 0);
    LOAD_BF(1, 1);
    for (int s = 0; s < nslab; s++) {
        int stg = s % NSTAGE;
        if (s + 1 < nslab) cp_wait1(); else cp_wait0();
        __syncthreads();
        if (s + 2 < nslab) LOAD_BF(s + 2, (s + 2) % NSTAGE);
        const uint32_t* Ac = As + (size_t)stg * GW;
        const uint32_t* Bc = Bs + (size_t)stg * GW;
#pragma unroll
        for (int kb = 0; kb < 2; kb++) {
            int wb = kb * 8;
            uint32_t af[4][4], bfr[4][2];
#pragma unroll
            for (int mf = 0; mf < 4; mf++) {
                int m = wm + mf * 16 + g;
                af[mf][0] = lds_sw(Ac, m, wb + lq);
                af[mf][1] = lds_sw(Ac, m + 8, wb + lq);
                af[mf][2] = lds_sw(Ac, m, wb + lq + 4);
                af[mf][3] = lds_sw(Ac, m + 8, wb + lq + 4);
            }
#pragma unroll
            for (int nf = 0; nf < 4; nf++) {
                int cc = wn + nf * 8 + g;
                bfr[nf][0] = lds_sw(Bc, cc, wb + lq);
                bfr[nf][1] = lds_sw(Bc, cc, wb + lq + 4);
            }
#pragma unroll
            for (int mf = 0; mf < 4; mf++)
#pragma unroll
                for (int nf = 0; nf < 4; nf++)
                    mma16(acc[mf][nf], af[mf][0], af[mf][1], af[mf][2], af[mf][3],
                          bfr[nf][0], bfr[nf][1]);
        }
    }
#undef LOAD_BF

#pragma unroll
    for (int nf = 0; nf < 4; nf++) {
#pragma unroll
        for (int cj = 0; cj < 2; cj++) {
            int co = c0 + wn + nf * 8 + lq * 2 + cj;
            float bv = bias[co];
            float s1 = scal1[co];
            float s2 = (mode == 1) ? scal2[co] : 0.f;
#pragma unroll
            for (int mf = 0; mf < 4; mf++) {
#pragma unroll
                for (int hr = 0; hr < 2; hr++) {
                    int m = m0 + wm + mf * 16 + g + hr * 8;
                    size_t idx = ((size_t)b * Cout + co) * (size_t)N + m;
                    float val = acc[mf][nf][hr * 2 + cj] + bv;
                    if (mode == 0)
                        out[idx] = resid1[idx] + val * s1;
                    else
                        out[idx] = resid1[idx] + (resid2[idx] + val * s1) * s2;
                }
            }
        }
    }
}

// ---------------- LayerNorm + elu+1 (in place on (rows, C)) ----------------
__global__ void ln_elu_kernel(float* __restrict__ x, const float* __restrict__ w,
                              const float* __restrict__ bvec) {
    int r = blockIdx.x;
    float* p = x + (size_t)r * Cn;
    int t = threadIdx.x;  // 128
    float v0 = p[t], v1 = p[t + 128], v2 = p[t + 256];
    float s = v0 + v1 + v2;
    float s2 = v0 * v0 + v1 * v1 + v2 * v2;
    __shared__ float red[128];
    red[t] = s;
    __syncthreads();
    for (int st = 64; st > 0; st >>= 1) {
        if (t < st) red[t] += red[t + st];
        __syncthreads();
    }
    float mu = red[0] * (1.f / (float)Cn);
    __syncthreads();
    red[t] = s2;
    __syncthreads();
    for (int st = 64; st > 0; st >>= 1) {
        if (t < st) red[t] += red[t + st];
        __syncthreads();
    }
    float var = red[0] * (1.f / (float)Cn) - mu * mu;
    float inv = rsqrtf(var + LN_EPS);
    float y;
    y = (v0 - mu) * inv * w[t] + bvec[t];
    p[t] = (y > 0.f) ? y + 1.f : expf(y);
    y = (v1 - mu) * inv * w[t + 128] + bvec[t + 128];
    p[t + 128] = (y > 0.f) ? y + 1.f : expf(y);
    y = (v2 - mu) * inv * w[t + 256] + bvec[t + 256];
    p[t + 256] = (y > 0.f) ? y + 1.f : expf(y);
}

// ---------------- kv_sum + k_sum per (b,h) ----------------
__global__ void kv_kernel(const float* __restrict__ k, const float* __restrict__ v,
                          float* __restrict__ kv, float* __restrict__ ksum) {
    int bh = blockIdx.x;
    int b = bh / Hn, h = bh % Hn;
    __shared__ float ks[32][Dn];
    __shared__ float vs[32][Dn];
    int tid = threadIdx.x;  // 256
    float acc[9] = {};
    float ksacc = 0.f;
    for (int n0 = 0; n0 < NK; n0 += 32) {
        for (int i = tid; i < 32 * Dn; i += 256) {
            int nn = i / Dn, dd = i % Dn;
            size_t base = ((size_t)b * NK + n0 + nn) * Cn + h * Dn + dd;
            ks[nn][dd] = k[base];
            vs[nn][dd] = v[base];
        }
        __syncthreads();
#pragma unroll 4
        for (int nn = 0; nn < 32; nn++) {
#pragma unroll
            for (int o = 0; o < 9; o++) {
                int idx = tid + o * 256;
                int dd = idx / Dn, ee = idx % Dn;
                acc[o] += ks[nn][dd] * vs[nn][ee];
            }
            if (tid < Dn) ksacc += ks[nn][tid];
        }
        __syncthreads();
    }
#pragma unroll
    for (int o = 0; o < 9; o++) kv[(size_t)bh * Dn * Dn + tid + o * 256] = acc[o];
    if (tid < Dn) ksum[bh * Dn + tid] = ksacc;
}

// ---------------- attention: num/den -> bf16 rows ----------------
__global__ void attn_kernel(const float* __restrict__ q, const float* __restrict__ kv,
                            const float* __restrict__ ksum, __nv_bfloat16* __restrict__ attn) {
    int bh = blockIdx.y;
    int b = bh / Hn, h = bh % Hn;
    int n0 = blockIdx.x * 64;
    __shared__ float kvs[Dn][Dn];
    __shared__ float kss[Dn];
    __shared__ float qs[64][Dn];
    __shared__ float dens[64];
    int tid = threadIdx.x;  // 256
    for (int i = tid; i < Dn * Dn; i += 256) kvs[i / Dn][i % Dn] = kv[(size_t)bh * Dn * Dn + i];
    if (tid < Dn) kss[tid] = ksum[bh * Dn + tid];
    for (int i = tid; i < 64 * Dn; i += 256) {
        int nn = i / Dn, dd = i % Dn;
        qs[nn][dd] = q[((size_t)b * NQ + n0 + nn) * Cn + h * Dn + dd];
    }
    __syncthreads();
    if (tid < 64) {
        float den = 0.f;
#pragma unroll
        for (int dd = 0; dd < Dn; dd++) den += qs[tid][dd] * kss[dd];
        dens[tid] = den + 1e-8f;
    }
    __syncthreads();
#pragma unroll
    for (int o = 0; o < 12; o++) {
        int idx = tid + o * 256;
        int nn = idx / Dn, ee = idx % Dn;
        float sacc = 0.f;
#pragma unroll
        for (int dd = 0; dd < Dn; dd++) sacc += qs[nn][dd] * kvs[dd][ee];
        attn[((size_t)b * NQ + n0 + nn) * Cn + h * Dn + ee] =
            __float2bfloat16_rn(sacc / dens[nn]);
    }
}

// ---------------- host launch ----------------
extern "C" void kernel_launch(void* const* d_in, const int* in_sizes, int n_in,
                              void* d_out, int out_size) {
    const float* query = (const float*)d_in[0];
    const float* key = (const float*)d_in[1];
    const float* value = (const float*)d_in[2];
    const float* ada_gamma = (const float*)d_in[3];
    const float* ada_beta = (const float*)d_in[4];
    const float* Wq = (const float*)d_in[5];
    const float* bq = (const float*)d_in[6];
    const float* Wk = (const float*)d_in[7];
    const float* bk = (const float*)d_in[8];
    const float* Wv = (const float*)d_in[9];
    const float* bv = (const float*)d_in[10];
    const float* Wo = (const float*)d_in[11];
    const float* bo = (const float*)d_in[12];
    const float* lnq_w = (const float*)d_in[13];
    const float* lnq_b = (const float*)d_in[14];
    const float* lnk_w = (const float*)d_in[15];
    const float* lnk_b = (const float*)d_in[16];
    const float* attn_scalar = (const float*)d_in[17];
    const float* ffn_gamma = (const float*)d_in[18];
    const float* ffn_beta = (const float*)d_in[19];
    const float* W1 = (const float*)d_in[20];
    const float* b1 = (const float*)d_in[21];
    const float* W2 = (const float*)d_in[22];
    const float* b2 = (const float*)d_in[23];
    const float* ffn_scalar = (const float*)d_in[24];
    const float* final_scalar = (const float*)d_in[25];
    float* out = (float*)d_out;

    float *q, *k, *v, *working, *kv, *ksum, *gx, *meanc;
    __nv_bfloat16 *ada_b, *key_b, *val_b, *attn_b, *nrm_b, *h_b, *wts;
    cudaGetSymbolAddress((void**)&q, g_q);
    cudaGetSymbolAddress((void**)&k, g_k);
    cudaGetSymbolAddress((void**)&v, g_v);
    cudaGetSymbolAddress((void**)&working, g_working);
    cudaGetSymbolAddress((void**)&kv, g_kv);
    cudaGetSymbolAddress((void**)&ksum, g_ksum);
    cudaGetSymbolAddress((void**)&gx, g_gx);
    cudaGetSymbolAddress((void**)&meanc, g_meanc);
    cudaGetSymbolAddress((void**)&ada_b, b_ada);
    cudaGetSymbolAddress((void**)&key_b, b_key);
    cudaGetSymbolAddress((void**)&val_b, b_val);
    cudaGetSymbolAddress((void**)&attn_b, b_attn);
    cudaGetSymbolAddress((void**)&nrm_b, b_nrm);
    cudaGetSymbolAddress((void**)&h_b, b_h);
    cudaGetSymbolAddress((void**)&wts, b_wts);

    __nv_bfloat16* wq_b = wts;
    __nv_bfloat16* wk_b = wts + CC;
    __nv_bfloat16* wv_b = wts + 2 * CC;
    __nv_bfloat16* wo_b = wts + 3 * CC;
    __nv_bfloat16* w1_b = wts + 4 * CC;
    __nv_bfloat16* w2_b = wts + 4 * CC + FC;

    cudaFuncSetAttribute(gemm_bf16_row, cudaFuncAttributeMaxDynamicSharedMemorySize, GEMM_SMEM);
    cudaFuncSetAttribute(gemm_bf16_cm, cudaFuncAttributeMaxDynamicSharedMemorySize, GEMM_SMEM);

    // 0) weight conversions
    conv_f2bf<<<(CC / 4 + 255) / 256, 256>>>((const float4*)Wq, (__nv_bfloat162*)wq_b, CC / 4);
    conv_f2bf<<<(CC / 4 + 255) / 256, 256>>>((const float4*)Wk, (__nv_bfloat162*)wk_b, CC / 4);
    conv_f2bf<<<(CC / 4 + 255) / 256, 256>>>((const float4*)Wv, (__nv_bfloat162*)wv_b, CC / 4);
    conv_f2bf<<<(CC / 4 + 255) / 256, 256>>>((const float4*)Wo, (__nv_bfloat162*)wo_b, CC / 4);
    conv_f2bf<<<(FC / 4 + 255) / 256, 256>>>((const float4*)W1, (__nv_bfloat162*)w1_b, FC / 4);
    conv_f2bf<<<(FC / 4 + 255) / 256, 256>>>((const float4*)W2, (__nv_bfloat162*)w2_b, FC / 4);

    // 0b) key/value transpose-convert to bf16 rows
    transconv_kernel<<<dim3(Cn / 64, NK / 32, Bn), 256>>>(key, key_b, nullptr, nullptr,
                                                          nullptr, nullptr, NK, 0);
    transconv_kernel<<<dim3(Cn / 64, NK / 32, Bn), 256>>>(value, val_b, nullptr, nullptr,
                                                          nullptr, nullptr, NK, 0);

    // 1) GRN on query -> ada (bf16 rows, fused transpose)
    grn_reduce_kernel<<<Bn * Cn, 256>>>(query, gx, NQ);
    grn_mean_kernel<<<Bn, 128>>>(gx, meanc);
    transconv_kernel<<<dim3(Cn / 64, NQ / 32, Bn), 256>>>(query, ada_b, gx, meanc,
                                                          ada_gamma, ada_beta, NQ, 1);

    // 2) projections (bf16 tensor core)
    gemm_bf16_row<<<dim3(NQ / BM, Cn / BN, Bn), 256, GEMM_SMEM>>>(ada_b, wq_b, bq, q, nullptr,
                                                                  NQ, Cn, Cn, 0);
    gemm_bf16_row<<<dim3(NK / BM, Cn / BN, Bn), 256, GEMM_SMEM>>>(key_b, wk_b, bk, k, nullptr,
                                                                  NK, Cn, Cn, 0);
    gemm_bf16_row<<<dim3(NK / BM, Cn / BN, Bn), 256, GEMM_SMEM>>>(val_b, wv_b, bv, v, nullptr,
                                                                  NK, Cn, Cn, 0);

    // 3) LN + elu+1 (in place, fp32)
    ln_elu_kernel<<<Bn * NQ, 128>>>(q, lnq_w, lnq_b);
    ln_elu_kernel<<<Bn * NK, 128>>>(k, lnk_w, lnk_b);

    // 4) kv_sum, k_sum
    kv_kernel<<<Bn * Hn, 256>>>(k, v, kv, ksum);

    // 5) linear attention num/den -> bf16 rows
    attn_kernel<<<dim3(NQ / 64, Bn * Hn), 256>>>(q, kv, ksum, attn_b);

    // 6) Wo projection + attn residual -> working (fp32, channel-major)
    gemm_bf16_cm<<<dim3(NQ / BM, Cn / BN, Bn), 256, GEMM_SMEM>>>(
        attn_b, wo_b, bo, query, nullptr, attn_scalar, nullptr, working, NQ, Cn, Cn, 0);

    // 7) GRN on working -> normed (bf16 rows, fused transpose)
    grn_reduce_kernel<<<Bn * Cn, 256>>>(working, gx, NQ);
    grn_mean_kernel<<<Bn, 128>>>(gx, meanc);
    transconv_kernel<<<dim3(Cn / 64, NQ / 32, Bn), 256>>>(working, nrm_b, gx, meanc,
                                                          ffn_gamma, ffn_beta, NQ, 1);

    // 8) FFN1 (+silu) -> h (bf16 rows)
    gemm_bf16_row<<<dim3(NQ / BM, Fn / BN, Bn), 256, GEMM_SMEM>>>(nrm_b, w1_b, b1, nullptr, h_b,
                                                                  NQ, Cn, Fn, 1);

    // 9) FFN2 + ffn residual + final residual -> out (fp32, channel-major)
    gemm_bf16_cm<<<dim3(NQ / BM, Cn / BN, Bn), 256, GEMM_SMEM>>>(
        h_b, w2_b, b2, query, working, ffn_scalar, final_scalar, out, NQ, Fn, Cn, 1);
}

// round 7
// speedup vs baseline: 1.4625x; 1.1769x over previous
#include <cuda_runtime.h>
#include <cuda_bf16.h>
#include <math.h>
#include <stdint.h>

// Problem constants
#define Bn 8
#define Cn 384
#define NQ 4096
#define NK 1024
#define Hn 8
#define Dn 48
#define Fn 1536
#define GRN_EPS 1e-6f
#define LN_EPS 1e-5f

// GEMM tiling (bf16)
#define BM 128
#define BN 128
#define KSB 32        // k elements per slab
#define KW 16         // uint32 words per row (KSB/2)
#define NSTAGE 3
#define GW (BM * KW)  // words per stage per operand (2048)
#define GEMM_SMEM (NSTAGE * 2 * GW * 4)  // 49152 bytes

#define CC (Cn * Cn)
#define FC (Fn * Cn)

// ---------------- scratch (device globals; no allocations) ----------------
__device__ float g_q[(size_t)Bn * NQ * Cn];
__device__ float g_k[(size_t)Bn * NK * Cn];
__device__ float g_v[(size_t)Bn * NK * Cn];
__device__ float g_working[(size_t)Bn * Cn * NQ];
__device__ float g_kv[(size_t)Bn * Hn * Dn * Dn];
__device__ float g_ksum[(size_t)Bn * Hn * Dn];
__device__ float g_gx[(size_t)Bn * Cn];
__device__ float g_meanc[Bn];

__device__ __nv_bfloat16 b_ada[(size_t)Bn * NQ * Cn];
__device__ __nv_bfloat16 b_key[(size_t)Bn * NK * Cn];
__device__ __nv_bfloat16 b_val[(size_t)Bn * NK * Cn];
__device__ __nv_bfloat16 b_attn[(size_t)Bn * NQ * Cn];
__device__ __nv_bfloat16 b_nrm[(size_t)Bn * NQ * Cn];
__device__ __nv_bfloat16 b_h[(size_t)Bn * NQ * Fn];
__device__ __nv_bfloat16 b_wts[4 * CC + 2 * FC];

// ---------------- helpers ----------------
__device__ __forceinline__ void cp_async16(void* smem_dst, const void* gsrc) {
    uint32_t s = (uint32_t)__cvta_generic_to_shared(smem_dst);
    asm volatile("cp.async.cg.shared.global [%0], [%1], 16;" ::"r"(s), "l"(gsrc));
}
__device__ __forceinline__ void cp_commit() { asm volatile("cp.async.commit_group;"); }
__device__ __forceinline__ void cp_wait1() { asm volatile("cp.async.wait_group 1;"); }
__device__ __forceinline__ void cp_wait0() { asm volatile("cp.async.wait_group 0;"); }

__device__ __forceinline__ void mma16(float* c, uint32_t a0, uint32_t a1, uint32_t a2,
                                      uint32_t a3, uint32_t b0, uint32_t b1) {
    asm volatile(
        "mma.sync.aligned.m16n8k16.row.col.f32.bf16.bf16.f32 "
        "{%0,%1,%2,%3},{%4,%5,%6,%7},{%8,%9},{%0,%1,%2,%3};"
        : "+f"(c[0]), "+f"(c[1]), "+f"(c[2]), "+f"(c[3])
        : "r"(a0), "r"(a1), "r"(a2), "r"(a3), "r"(b0), "r"(b1));
}

__device__ __forceinline__ void ldsm4(uint32_t& r0, uint32_t& r1, uint32_t& r2, uint32_t& r3,
                                      uint32_t saddr) {
    asm volatile("ldmatrix.sync.aligned.m8n8.x4.shared.b16 {%0,%1,%2,%3}, [%4];"
                 : "=r"(r0), "=r"(r1), "=r"(r2), "=r"(r3)
                 : "r"(saddr));
}

// ---------------- merged weight convert (one launch for all 6 weights) ----------------
__global__ void conv_f2bf_all(const float4* __restrict__ wq, const float4* __restrict__ wk,
                              const float4* __restrict__ wv, const float4* __restrict__ wo,
                              const float4* __restrict__ w1, const float4* __restrict__ w2,
                              __nv_bfloat162* __restrict__ dst) {
    const int C4 = CC / 4, F4 = FC / 4;
    int total = 4 * C4 + 2 * F4;
    for (int i = blockIdx.x * 256 + threadIdx.x; i < total; i += gridDim.x * 256) {
        const float4* src;
        int off;
        if (i < 4 * C4) {
            int seg = i / C4;
            off = i - seg * C4;
            src = (seg == 0) ? wq : (seg == 1) ? wk : (seg == 2) ? wv : wo;
        } else if (i < 4 * C4 + F4) {
            src = w1;
            off = i - 4 * C4;
        } else {
            src = w2;
            off = i - 4 * C4 - F4;
        }
        float4 v = src[off];
        __nv_bfloat162 a, b;
        a.x = __float2bfloat16_rn(v.x); a.y = __float2bfloat16_rn(v.y);
        b.x = __float2bfloat16_rn(v.z); b.y = __float2bfloat16_rn(v.w);
        dst[2 * i] = a;
        dst[2 * i + 1] = b;
    }
}

// ---------------- GRN ----------------
__global__ void grn_reduce_kernel(const float* __restrict__ x, float* __restrict__ gx, int N) {
    int bc = blockIdx.x;
    const float4* p = (const float4*)(x + (size_t)bc * N);
    int n4 = N >> 2;
    float s = 0.f;
    for (int i = threadIdx.x; i < n4; i += 256) {
        float4 v = p[i];
        s += v.x * v.x + v.y * v.y + v.z * v.z + v.w * v.w;
    }
    __shared__ float red[256];
    red[threadIdx.x] = s;
    __syncthreads();
    for (int st = 128; st > 0; st >>= 1) {
        if (threadIdx.x < st) red[threadIdx.x] += red[threadIdx.x + st];
        __syncthreads();
    }
    if (threadIdx.x == 0) gx[bc] = sqrtf(red[0]);
}

__global__ void grn_mean_kernel(const float* __restrict__ gx, float* __restrict__ meanc) {
    int b = blockIdx.x;
    int t = threadIdx.x;  // 128
    float s = 0.f;
    for (int c = t; c < Cn; c += 128) s += gx[b * Cn + c];
    __shared__ float red[128];
    red[t] = s;
    __syncthreads();
    for (int st = 64; st > 0; st >>= 1) {
        if (t < st) red[t] += red[t + st];
        __syncthreads();
    }
    if (t == 0) meanc[b] = red[0] * (1.f / (float)Cn) + GRN_EPS;
}

// ---------------- transpose + (optional GRN) + convert to bf16 rows ----------------
__global__ void transconv_kernel(const float* __restrict__ x, __nv_bfloat16* __restrict__ out,
                                 const float* __restrict__ gx, const float* __restrict__ meanc,
                                 const float* __restrict__ gamma, const float* __restrict__ beta,
                                 int N, int grn) {
    int b = blockIdx.z;
    int c0 = blockIdx.x * 64;
    int n0 = blockIdx.y * 32;
    __shared__ float t[64][33];
    int tid = threadIdx.x;
    int j = tid & 31, i0 = tid >> 5;
#pragma unroll
    for (int p = 0; p < 8; p++) {
        int i = i0 + p * 8;
        t[i][j] = x[((size_t)b * Cn + c0 + i) * N + n0 + j];
    }
    __syncthreads();
    int cp = tid & 31;
    int nn0 = tid >> 5;
    int c = c0 + 2 * cp;
    float sc0 = 1.f, bt0 = 0.f, sc1 = 1.f, bt1 = 0.f;
    if (grn) {
        sc0 = 1.f + (1.f + gamma[c]) * gx[b * Cn + c] / meanc[b];
        bt0 = beta[c];
        sc1 = 1.f + (1.f + gamma[c + 1]) * gx[b * Cn + c + 1] / meanc[b];
        bt1 = beta[c + 1];
    }
#pragma unroll
    for (int p = 0; p < 4; p++) {
        int nn = nn0 + p * 8;
        float v0 = t[2 * cp][nn] * sc0 + bt0;
        float v1 = t[2 * cp + 1][nn] * sc1 + bt1;
        __nv_bfloat162 hv;
        hv.x = __float2bfloat16_rn(v0);
        hv.y = __float2bfloat16_rn(v1);
        *(__nv_bfloat162*)(out + ((size_t)b * N + n0 + nn) * Cn + c) = hv;
    }
}

// ---------------- shared GEMM mainloop (ldmatrix fragments) ----------------
// Both GEMMs use identical A/B smem layout: [row][KW words], XOR swizzle on 16B chunks.
#define GEMM_MAINLOOP(Ab, Wb, K)                                                          \
    const uint32_t a_base = (uint32_t)__cvta_generic_to_shared(As);                       \
    const uint32_t b_base = (uint32_t)__cvta_generic_to_shared(Bs);                       \
    int lr = (lane & 7) + ((lane >> 3) & 1) * 8;                                          \
    int lca = lane >> 4;                                                                  \
    int lrb = (lane & 7) + (lane >> 4) * 8;                                               \
    int lcb = (lane >> 3) & 1;                                                            \
    int nslab = (K) / KSB;                                                                \
    LOAD_BF(0, 0);                                                                        \
    LOAD_BF(1, 1);                                                                        \
    for (int s = 0; s < nslab; s++) {                                                     \
        int stg = s % NSTAGE;                                                             \
        if (s + 1 < nslab) cp_wait1(); else cp_wait0();                                   \
        __syncthreads();                                                                  \
        if (s + 2 < nslab) LOAD_BF(s + 2, (s + 2) % NSTAGE);                              \
        uint32_t Ast = a_base + stg * GW * 4;                                             \
        uint32_t Bst = b_base + stg * GW * 4;                                             \
        _Pragma("unroll") for (int kb = 0; kb < 2; kb++) {                                \
            uint32_t af[4][4], bfr[4][2];                                                 \
            _Pragma("unroll") for (int mf = 0; mf < 4; mf++) {                            \
                int row = wm + mf * 16 + lr;                                              \
                int ch = 2 * kb + lca;                                                    \
                ldsm4(af[mf][0], af[mf][1], af[mf][2], af[mf][3],                         \
                      Ast + row * 64 + ((ch ^ ((row >> 1) & 3)) << 4));                   \
            }                                                                             \
            _Pragma("unroll") for (int p = 0; p < 2; p++) {                               \
                int row = wn + p * 16 + lrb;                                              \
                int ch = 2 * kb + lcb;                                                    \
                ldsm4(bfr[2 * p][0], bfr[2 * p][1], bfr[2 * p + 1][0], bfr[2 * p + 1][1], \
                      Bst + row * 64 + ((ch ^ ((row >> 1) & 3)) << 4));                   \
            }                                                                             \
            _Pragma("unroll") for (int mf = 0; mf < 4; mf++)                              \
                _Pragma("unroll") for (int nf = 0; nf < 4; nf++)                          \
                    mma16(acc[mf][nf], af[mf][0], af[mf][1], af[mf][2], af[mf][3],        \
                          bfr[nf][0], bfr[nf][1]);                                        \
        }                                                                                 \
    }

#define LOAD_BF(slab, stg)                                                              \
    {                                                                                   \
        int kk0 = (slab)*KSB;                                                           \
        uint32_t* Ad = As + (size_t)(stg)*GW;                                           \
        uint32_t* Bd = Bs + (size_t)(stg)*GW;                                           \
        _Pragma("unroll") for (int p = 0; p < 2; p++) {                                 \
            int c = tid + p * 256;                                                      \
            int r = c >> 2, ch = c & 3;                                                 \
            int sw = ((ch ^ ((r >> 1) & 3)) << 2);                                      \
            cp_async16(Ad + r * KW + sw, Ab + (size_t)(m0 + r) * K + kk0 + ch * 8);     \
            cp_async16(Bd + r * KW + sw, W + (size_t)(c0 + r) * K + kk0 + ch * 8);      \
        }                                                                               \
        cp_commit();                                                                    \
    }

// ---------------- bf16 GEMM, row-major output ----------------
__global__ __launch_bounds__(256) void gemm_bf16_row(
    const __nv_bfloat16* __restrict__ A, const __nv_bfloat16* __restrict__ W,
    const float* __restrict__ bias, float* __restrict__ Yf, __nv_bfloat16* __restrict__ Yh,
    int N, int K, int Cout, int mode) {
    extern __shared__ uint32_t smu[];
    uint32_t* As = smu;
    uint32_t* Bs = smu + NSTAGE * GW;
    int b = blockIdx.z;
    int m0 = blockIdx.x * BM;
    int c0 = blockIdx.y * BN;
    int tid = threadIdx.x;
    int warp = tid >> 5, lane = tid & 31;
    int g = lane >> 2, lq = lane & 3;
    int wm = (warp >> 2) * 64;
    int wn = (warp & 3) * 32;
    float acc[4][4][4] = {};
    const __nv_bfloat16* Ab = A + (size_t)b * N * K;

    GEMM_MAINLOOP(Ab, W, K)

#pragma unroll
    for (int mf = 0; mf < 4; mf++) {
#pragma unroll
        for (int nf = 0; nf < 4; nf++) {
            int co = c0 + wn + nf * 8 + lq * 2;
            float b0v = bias[co], b1v = bias[co + 1];
#pragma unroll
            for (int hr = 0; hr < 2; hr++) {
                int m = m0 + wm + mf * 16 + g + hr * 8;
                float v0 = acc[mf][nf][hr * 2 + 0] + b0v;
                float v1 = acc[mf][nf][hr * 2 + 1] + b1v;
                if (mode == 1) {
                    v0 = v0 / (1.f + expf(-v0));
                    v1 = v1 / (1.f + expf(-v1));
                    __nv_bfloat162 hv;
                    hv.x = __float2bfloat16_rn(v0);
                    hv.y = __float2bfloat16_rn(v1);
                    *(__nv_bfloat162*)(Yh + ((size_t)b * N + m) * Cout + co) = hv;
                } else {
                    *(float2*)(Yf + ((size_t)b * N + m) * Cout + co) = make_float2(v0, v1);
                }
            }
        }
    }
}

// ---------------- bf16 GEMM, channel-major fused output ----------------
__global__ __launch_bounds__(256) void gemm_bf16_cm(
    const __nv_bfloat16* __restrict__ A, const __nv_bfloat16* __restrict__ W,
    const float* __restrict__ bias,
    const float* __restrict__ resid1, const float* __restrict__ resid2,
    const float* __restrict__ scal1, const float* __restrict__ scal2,
    float* __restrict__ out, int N, int K, int Cout, int mode) {
    extern __shared__ uint32_t smu[];
    uint32_t* As = smu;
    uint32_t* Bs = smu + NSTAGE * GW;
    int b = blockIdx.z;
    int m0 = blockIdx.x * BM;
    int c0 = blockIdx.y * BN;
    int tid = threadIdx.x;
    int warp = tid >> 5, lane = tid & 31;
    int g = lane >> 2, lq = lane & 3;
    int wm = (warp >> 2) * 64;
    int wn = (warp & 3) * 32;
    float acc[4][4][4] = {};
    const __nv_bfloat16* Ab = A + (size_t)b * N * K;

    GEMM_MAINLOOP(Ab, W, K)

#pragma unroll
    for (int nf = 0; nf < 4; nf++) {
#pragma unroll
        for (int cj = 0; cj < 2; cj++) {
            int co = c0 + wn + nf * 8 + lq * 2 + cj;
            float bv = bias[co];
            float s1 = scal1[co];
            float s2 = (mode == 1) ? scal2[co] : 0.f;
#pragma unroll
            for (int mf = 0; mf < 4; mf++) {
#pragma unroll
                for (int hr = 0; hr < 2; hr++) {
                    int m = m0 + wm + mf * 16 + g + hr * 8;
                    size_t idx = ((size_t)b * Cout + co) * (size_t)N + m;
                    float val = acc[mf][nf][hr * 2 + cj] + bv;
                    if (mode == 0)
                        out[idx] = resid1[idx] + val * s1;
                    else
                        out[idx] = resid1[idx] + (resid2[idx] + val * s1) * s2;
                }
            }
        }
    }
}

// ---------------- LayerNorm + elu+1 (in place on (rows, C)) ----------------
__global__ void ln_elu_kernel(float* __restrict__ x, const float* __restrict__ w,
                              const float* __restrict__ bvec) {
    int r = blockIdx.x;
    float* p = x + (size_t)r * Cn;
    int t = threadIdx.x;  // 128
    float v0 = p[t], v1 = p[t + 128], v2 = p[t + 256];
    float s = v0 + v1 + v2;
    float s2 = v0 * v0 + v1 * v1 + v2 * v2;
    __shared__ float red[128];
    red[t] = s;
    __syncthreads();
    for (int st = 64; st > 0; st >>= 1) {
        if (t < st) red[t] += red[t + st];
        __syncthreads();
    }
    float mu = red[0] * (1.f / (float)Cn);
    __syncthreads();
    red[t] = s2;
    __syncthreads();
    for (int st = 64; st > 0; st >>= 1) {
        if (t < st) red[t] += red[t + st];
        __syncthreads();
    }
    float var = red[0] * (1.f / (float)Cn) - mu * mu;
    float inv = rsqrtf(var + LN_EPS);
    float y;
    y = (v0 - mu) * inv * w[t] + bvec[t];
    p[t] = (y > 0.f) ? y + 1.f : expf(y);
    y = (v1 - mu) * inv * w[t + 128] + bvec[t + 128];
    p[t + 128] = (y > 0.f) ? y + 1.f : expf(y);
    y = (v2 - mu) * inv * w[t + 256] + bvec[t + 256];
    p[t + 256] = (y > 0.f) ? y + 1.f : expf(y);
}

// ---------------- kv_sum + k_sum per (b,h) ----------------
__global__ void kv_kernel(const float* __restrict__ k, const float* __restrict__ v,
                          float* __restrict__ kv, float* __restrict__ ksum) {
    int bh = blockIdx.x;
    int b = bh / Hn, h = bh % Hn;
    __shared__ float ks[32][Dn];
    __shared__ float vs[32][Dn];
    int tid = threadIdx.x;  // 256
    float acc[9] = {};
    float ksacc = 0.f;
    for (int n0 = 0; n0 < NK; n0 += 32) {
        for (int i = tid; i < 32 * Dn; i += 256) {
            int nn = i / Dn, dd = i % Dn;
            size_t base = ((size_t)b * NK + n0 + nn) * Cn + h * Dn + dd;
            ks[nn][dd] = k[base];
            vs[nn][dd] = v[base];
        }
        __syncthreads();
#pragma unroll 4
        for (int nn = 0; nn < 32; nn++) {
#pragma unroll
            for (int o = 0; o < 9; o++) {
                int idx = tid + o * 256;
                int dd = idx / Dn, ee = idx % Dn;
                acc[o] += ks[nn][dd] * vs[nn][ee];
            }
            if (tid < Dn) ksacc += ks[nn][tid];
        }
        __syncthreads();
    }
#pragma unroll
    for (int o = 0; o < 9; o++) kv[(size_t)bh * Dn * Dn + tid + o * 256] = acc[o];
    if (tid < Dn) ksum[bh * Dn + tid] = ksacc;
}

// ---------------- attention: num/den -> bf16 rows ----------------
__global__ void attn_kernel(const float* __restrict__ q, const float* __restrict__ kv,
                            const float* __restrict__ ksum, __nv_bfloat16* __restrict__ attn) {
    int bh = blockIdx.y;
    int b = bh / Hn, h = bh % Hn;
    int n0 = blockIdx.x * 64;
    __shared__ float kvs[Dn][Dn];
    __shared__ float kss[Dn];
    __shared__ float qs[64][Dn];
    __shared__ float dens[64];
    int tid = threadIdx.x;  // 256
    for (int i = tid; i < Dn * Dn; i += 256) kvs[i / Dn][i % Dn] = kv[(size_t)bh * Dn * Dn + i];
    if (tid < Dn) kss[tid] = ksum[bh * Dn + tid];
    for (int i = tid; i < 64 * Dn; i += 256) {
        int nn = i / Dn, dd = i % Dn;
        qs[nn][dd] = q[((size_t)b * NQ + n0 + nn) * Cn + h * Dn + dd];
    }
    __syncthreads();
    if (tid < 64) {
        float den = 0.f;
#pragma unroll
        for (int dd = 0; dd < Dn; dd++) den += qs[tid][dd] * kss[dd];
        dens[tid] = den + 1e-8f;
    }
    __syncthreads();
#pragma unroll
    for (int o = 0; o < 12; o++) {
        int idx = tid + o * 256;
        int nn = idx / Dn, ee = idx % Dn;
        float sacc = 0.f;
#pragma unroll
        for (int dd = 0; dd < Dn; dd++) sacc += qs[nn][dd] * kvs[dd][ee];
        attn[((size_t)b * NQ + n0 + nn) * Cn + h * Dn + ee] =
            __float2bfloat16_rn(sacc / dens[nn]);
    }
}

// ---------------- host launch ----------------
extern "C" void kernel_launch(void* const* d_in, const int* in_sizes, int n_in,
                              void* d_out, int out_size) {
    const float* query = (const float*)d_in[0];
    const float* key = (const float*)d_in[1];
    const float* value = (const float*)d_in[2];
    const float* ada_gamma = (const float*)d_in[3];
    const float* ada_beta = (const float*)d_in[4];
    const float* Wq = (const float*)d_in[5];
    const float* bq = (const float*)d_in[6];
    const float* Wk = (const float*)d_in[7];
    const float* bk = (const float*)d_in[8];
    const float* Wv = (const float*)d_in[9];
    const float* bv = (const float*)d_in[10];
    const float* Wo = (const float*)d_in[11];
    const float* bo = (const float*)d_in[12];
    const float* lnq_w = (const float*)d_in[13];
    const float* lnq_b = (const float*)d_in[14];
    const float* lnk_w = (const float*)d_in[15];
    const float* lnk_b = (const float*)d_in[16];
    const float* attn_scalar = (const float*)d_in[17];
    const float* ffn_gamma = (const float*)d_in[18];
    const float* ffn_beta = (const float*)d_in[19];
    const float* W1 = (const float*)d_in[20];
    const float* b1 = (const float*)d_in[21];
    const float* W2 = (const float*)d_in[22];
    const float* b2 = (const float*)d_in[23];
    const float* ffn_scalar = (const float*)d_in[24];
    const float* final_scalar = (const float*)d_in[25];
    float* out = (float*)d_out;

    float *q, *k, *v, *working, *kv, *ksum, *gx, *meanc;
    __nv_bfloat16 *ada_b, *key_b, *val_b, *attn_b, *nrm_b, *h_b, *wts;
    cudaGetSymbolAddress((void**)&q, g_q);
    cudaGetSymbolAddress((void**)&k, g_k);
    cudaGetSymbolAddress((void**)&v, g_v);
    cudaGetSymbolAddress((void**)&working, g_working);
    cudaGetSymbolAddress((void**)&kv, g_kv);
    cudaGetSymbolAddress((void**)&ksum, g_ksum);
    cudaGetSymbolAddress((void**)&gx, g_gx);
    cudaGetSymbolAddress((void**)&meanc, g_meanc);
    cudaGetSymbolAddress((void**)&ada_b, b_ada);
    cudaGetSymbolAddress((void**)&key_b, b_key);
    cudaGetSymbolAddress((void**)&val_b, b_val);
    cudaGetSymbolAddress((void**)&attn_b, b_attn);
    cudaGetSymbolAddress((void**)&nrm_b, b_nrm);
    cudaGetSymbolAddress((void**)&h_b, b_h);
    cudaGetSymbolAddress((void**)&wts, b_wts);

    __nv_bfloat16* wq_b = wts;
    __nv_bfloat16* wk_b = wts + CC;
    __nv_bfloat16* wv_b = wts + 2 * CC;
    __nv_bfloat16* wo_b = wts + 3 * CC;
    __nv_bfloat16* w1_b = wts + 4 * CC;
    __nv_bfloat16* w2_b = wts + 4 * CC + FC;

    cudaFuncSetAttribute(gemm_bf16_row, cudaFuncAttributeMaxDynamicSharedMemorySize, GEMM_SMEM);
    cudaFuncSetAttribute(gemm_bf16_cm, cudaFuncAttributeMaxDynamicSharedMemorySize, GEMM_SMEM);

    // 0) all weight conversions in ONE launch
    conv_f2bf_all<<<1728, 256>>>((const float4*)Wq, (const float4*)Wk, (const float4*)Wv,
                                 (const float4*)Wo, (const float4*)W1, (const float4*)W2,
                                 (__nv_bfloat162*)wts);

    // 0b) key/value transpose-convert to bf16 rows
    transconv_kernel<<<dim3(Cn / 64, NK / 32, Bn), 256>>>(key, key_b, nullptr, nullptr,
                                                          nullptr, nullptr, NK, 0);
    transconv_kernel<<<dim3(Cn / 64, NK / 32, Bn), 256>>>(value, val_b, nullptr, nullptr,
                                                          nullptr, nullptr, NK, 0);

    // 1) GRN on query -> ada (bf16 rows, fused transpose)
    grn_reduce_kernel<<<Bn * Cn, 256>>>(query, gx, NQ);
    grn_mean_kernel<<<Bn, 128>>>(gx, meanc);
    transconv_kernel<<<dim3(Cn / 64, NQ / 32, Bn), 256>>>(query, ada_b, gx, meanc,
                                                          ada_gamma, ada_beta, NQ, 1);

    // 2) projections (bf16 tensor core, ldmatrix)
    gemm_bf16_row<<<dim3(NQ / BM, Cn / BN, Bn), 256, GEMM_SMEM>>>(ada_b, wq_b, bq, q, nullptr,
                                                                  NQ, Cn, Cn, 0);
    gemm_bf16_row<<<dim3(NK / BM, Cn / BN, Bn), 256, GEMM_SMEM>>>(key_b, wk_b, bk, k, nullptr,
                                                                  NK, Cn, Cn, 0);
    gemm_bf16_row<<<dim3(NK / BM, Cn / BN, Bn), 256, GEMM_SMEM>>>(val_b, wv_b, bv, v, nullptr,
                                                                  NK, Cn, Cn, 0);

    // 3) LN + elu+1 (in place, fp32)
    ln_elu_kernel<<<Bn * NQ, 128>>>(q, lnq_w, lnq_b);
    ln_elu_kernel<<<Bn * NK, 128>>>(k, lnk_w, lnk_b);

    // 4) kv_sum, k_sum
    kv_kernel<<<Bn * Hn, 256>>>(k, v, kv, ksum);

    // 5) linear attention num/den -> bf16 rows
    attn_kernel<<<dim3(NQ / 64, Bn * Hn), 256>>>(q, kv, ksum, attn_b);

    // 6) Wo projection + attn residual -> working (fp32, channel-major)
    gemm_bf16_cm<<<dim3(NQ / BM, Cn / BN, Bn), 256, GEMM_SMEM>>>(
        attn_b, wo_b, bo, query, nullptr, attn_scalar, nullptr, working, NQ, Cn, Cn, 0);

    // 7) GRN on working -> normed (bf16 rows, fused transpose)
    grn_reduce_kernel<<<Bn * Cn, 256>>>(working, gx, NQ);
    grn_mean_kernel<<<Bn, 128>>>(gx, meanc);
    transconv_kernel<<<dim3(Cn / 64, NQ / 32, Bn), 256>>>(working, nrm_b, gx, meanc,
                                                          ffn_gamma, ffn_beta, NQ, 1);

    // 8) FFN1 (+silu) -> h (bf16 rows)
    gemm_bf16_row<<<dim3(NQ / BM, Fn / BN, Bn), 256, GEMM_SMEM>>>(nrm_b, w1_b, b1, nullptr, h_b,
                                                                  NQ, Cn, Fn, 1);

    // 9) FFN2 + ffn residual + final residual -> out (fp32, channel-major)
    gemm_bf16_cm<<<dim3(NQ / BM, Cn / BN, Bn), 256, GEMM_SMEM>>>(
        h_b, w2_b, b2, query, working, ffn_scalar, final_scalar, out, NQ, Fn, Cn, 1);
}

// round 9
// speedup vs baseline: 2.0471x; 1.3997x over previous
#include <cuda_runtime.h>
#include <cuda_bf16.h>
#include <math.h>
#include <stdint.h>

// Problem constants
#define Bn 8
#define Cn 384
#define NQ 4096
#define NK 1024
#define Hn 8
#define Dn 48
#define Fn 1536
#define GRN_EPS 1e-6f
#define LN_EPS 1e-5f

// GEMM tiling (bf16)
#define BM 128
#define BN 128
#define KSB 32        // k elements per slab
#define KW 16         // uint32 words per row (KSB/2)
#define NSTAGE 3
#define GW (BM * KW)  // words per stage per operand (2048)
#define GEMM_SMEM (NSTAGE * 2 * GW * 4)  // 49152 bytes

#define CC (Cn * Cn)
#define FC (Fn * Cn)

// ---------------- scratch (device globals; no allocations) ----------------
__device__ float g_q[(size_t)Bn * NQ * Cn];
__device__ float g_k[(size_t)Bn * NK * Cn];
__device__ float g_v[(size_t)Bn * NK * Cn];
__device__ float g_working[(size_t)Bn * Cn * NQ];
__device__ float g_kv[(size_t)Bn * Hn * Dn * Dn];
__device__ float g_ksum[(size_t)Bn * Hn * Dn];
__device__ float g_gx[(size_t)Bn * Cn];
__device__ float g_meanc[Bn];

__device__ __nv_bfloat16 b_ada[(size_t)Bn * NQ * Cn];
__device__ __nv_bfloat16 b_key[(size_t)Bn * NK * Cn];
__device__ __nv_bfloat16 b_val[(size_t)Bn * NK * Cn];
__device__ __nv_bfloat16 b_qp[(size_t)Bn * NQ * Cn];   // q' = (elu(LN(q))+1)/den
__device__ __nv_bfloat16 b_nrm[(size_t)Bn * NQ * Cn];
__device__ __nv_bfloat16 b_h[(size_t)Bn * NQ * Fn];
__device__ __nv_bfloat16 b_wts[4 * CC + 2 * FC];
__device__ __nv_bfloat16 b_M[(size_t)Bn * Cn * Cn];    // per-batch folded kv@Wo weight

// ---------------- helpers ----------------
__device__ __forceinline__ void cp_async16(void* smem_dst, const void* gsrc) {
    uint32_t s = (uint32_t)__cvta_generic_to_shared(smem_dst);
    asm volatile("cp.async.cg.shared.global [%0], [%1], 16;" ::"r"(s), "l"(gsrc));
}
__device__ __forceinline__ void cp_commit() { asm volatile("cp.async.commit_group;"); }
__device__ __forceinline__ void cp_wait1() { asm volatile("cp.async.wait_group 1;"); }
__device__ __forceinline__ void cp_wait0() { asm volatile("cp.async.wait_group 0;"); }

__device__ __forceinline__ void mma16(float* c, uint32_t a0, uint32_t a1, uint32_t a2,
                                      uint32_t a3, uint32_t b0, uint32_t b1) {
    asm volatile(
        "mma.sync.aligned.m16n8k16.row.col.f32.bf16.bf16.f32 "
        "{%0,%1,%2,%3},{%4,%5,%6,%7},{%8,%9},{%0,%1,%2,%3};"
        : "+f"(c[0]), "+f"(c[1]), "+f"(c[2]), "+f"(c[3])
        : "r"(a0), "r"(a1), "r"(a2), "r"(a3), "r"(b0), "r"(b1));
}

__device__ __forceinline__ void ldsm4(uint32_t& r0, uint32_t& r1, uint32_t& r2, uint32_t& r3,
                                      uint32_t saddr) {
    asm volatile("ldmatrix.sync.aligned.m8n8.x4.shared.b16 {%0,%1,%2,%3}, [%4];"
                 : "=r"(r0), "=r"(r1), "=r"(r2), "=r"(r3)
                 : "r"(saddr));
}

// ---------------- merged weight convert ----------------
__global__ void conv_f2bf_all(const float4* __restrict__ wq, const float4* __restrict__ wk,
                              const float4* __restrict__ wv, const float4* __restrict__ wo,
                              const float4* __restrict__ w1, const float4* __restrict__ w2,
                              __nv_bfloat162* __restrict__ dst) {
    const int C4 = CC / 4, F4 = FC / 4;
    int total = 4 * C4 + 2 * F4;
    for (int i = blockIdx.x * 256 + threadIdx.x; i < total; i += gridDim.x * 256) {
        const float4* src;
        int off;
        if (i < 4 * C4) {
            int seg = i / C4;
            off = i - seg * C4;
            src = (seg == 0) ? wq : (seg == 1) ? wk : (seg == 2) ? wv : wo;
        } else if (i < 4 * C4 + F4) {
            src = w1;
            off = i - 4 * C4;
        } else {
            src = w2;
            off = i - 4 * C4 - F4;
        }
        float4 v = src[off];
        __nv_bfloat162 a, b;
        a.x = __float2bfloat16_rn(v.x); a.y = __float2bfloat16_rn(v.y);
        b.x = __float2bfloat16_rn(v.z); b.y = __float2bfloat16_rn(v.w);
        dst[2 * i] = a;
        dst[2 * i + 1] = b;
    }
}

// ---------------- GRN ----------------
__global__ void grn_reduce_kernel(const float* __restrict__ x, float* __restrict__ gx, int N) {
    int bc = blockIdx.x;
    const float4* p = (const float4*)(x + (size_t)bc * N);
    int n4 = N >> 2;
    float s = 0.f;
    for (int i = threadIdx.x; i < n4; i += 256) {
        float4 v = p[i];
        s += v.x * v.x + v.y * v.y + v.z * v.z + v.w * v.w;
    }
    __shared__ float red[256];
    red[threadIdx.x] = s;
    __syncthreads();
    for (int st = 128; st > 0; st >>= 1) {
        if (threadIdx.x < st) red[threadIdx.x] += red[threadIdx.x + st];
        __syncthreads();
    }
    if (threadIdx.x == 0) gx[bc] = sqrtf(red[0]);
}

__global__ void grn_mean_kernel(const float* __restrict__ gx, float* __restrict__ meanc) {
    int b = blockIdx.x;
    int t = threadIdx.x;  // 128
    float s = 0.f;
    for (int c = t; c < Cn; c += 128) s += gx[b * Cn + c];
    __shared__ float red[128];
    red[t] = s;
    __syncthreads();
    for (int st = 64; st > 0; st >>= 1) {
        if (t < st) red[t] += red[t + st];
        __syncthreads();
    }
    if (t == 0) meanc[b] = red[0] * (1.f / (float)Cn) + GRN_EPS;
}

// ---------------- transpose + (optional GRN) + convert to bf16 rows ----------------
__global__ void transconv_kernel(const float* __restrict__ x, __nv_bfloat16* __restrict__ out,
                                 const float* __restrict__ gx, const float* __restrict__ meanc,
                                 const float* __restrict__ gamma, const float* __restrict__ beta,
                                 int N, int grn) {
    int b = blockIdx.z;
    int c0 = blockIdx.x * 64;
    int n0 = blockIdx.y * 32;
    __shared__ float t[64][33];
    int tid = threadIdx.x;
    int j = tid & 31, i0 = tid >> 5;
#pragma unroll
    for (int p = 0; p < 8; p++) {
        int i = i0 + p * 8;
        t[i][j] = x[((size_t)b * Cn + c0 + i) * N + n0 + j];
    }
    __syncthreads();
    int cp = tid & 31;
    int nn0 = tid >> 5;
    int c = c0 + 2 * cp;
    float sc0 = 1.f, bt0 = 0.f, sc1 = 1.f, bt1 = 0.f;
    if (grn) {
        sc0 = 1.f + (1.f + gamma[c]) * gx[b * Cn + c] / meanc[b];
        bt0 = beta[c];
        sc1 = 1.f + (1.f + gamma[c + 1]) * gx[b * Cn + c + 1] / meanc[b];
        bt1 = beta[c + 1];
    }
#pragma unroll
    for (int p = 0; p < 4; p++) {
        int nn = nn0 + p * 8;
        float v0 = t[2 * cp][nn] * sc0 + bt0;
        float v1 = t[2 * cp + 1][nn] * sc1 + bt1;
        __nv_bfloat162 hv;
        hv.x = __float2bfloat16_rn(v0);
        hv.y = __float2bfloat16_rn(v1);
        *(__nv_bfloat162*)(out + ((size_t)b * N + n0 + nn) * Cn + c) = hv;
    }
}

// ---------------- shared GEMM mainloop (ldmatrix fragments) ----------------
#define GEMM_MAINLOOP(Ab, Wp, K)                                                          \
    const uint32_t a_base = (uint32_t)__cvta_generic_to_shared(As);                       \
    const uint32_t b_base = (uint32_t)__cvta_generic_to_shared(Bs);                       \
    int lr = (lane & 7) + ((lane >> 3) & 1) * 8;                                          \
    int lca = lane >> 4;                                                                  \
    int lrb = (lane & 7) + (lane >> 4) * 8;                                               \
    int lcb = (lane >> 3) & 1;                                                            \
    int nslab = (K) / KSB;                                                                \
    LOAD_BF(0, 0);                                                                        \
    LOAD_BF(1, 1);                                                                        \
    for (int s = 0; s < nslab; s++) {                                                     \
        int stg = s % NSTAGE;                                                             \
        if (s + 1 < nslab) cp_wait1(); else cp_wait0();                                   \
        __syncthreads();                                                                  \
        if (s + 2 < nslab) LOAD_BF(s + 2, (s + 2) % NSTAGE);                              \
        uint32_t Ast = a_base + stg * GW * 4;                                             \
        uint32_t Bst = b_base + stg * GW * 4;                                             \
        _Pragma("unroll") for (int kb = 0; kb < 2; kb++) {                                \
            uint32_t af[4][4], bfr[4][2];                                                 \
            _Pragma("unroll") for (int mf = 0; mf < 4; mf++) {                            \
                int row = wm + mf * 16 + lr;                                              \
                int ch = 2 * kb + lca;                                                    \
                ldsm4(af[mf][0], af[mf][1], af[mf][2], af[mf][3],                         \
                      Ast + row * 64 + ((ch ^ ((row >> 1) & 3)) << 4));                   \
            }                                                                             \
            _Pragma("unroll") for (int p = 0; p < 2; p++) {                               \
                int row = wn + p * 16 + lrb;                                              \
                int ch = 2 * kb + lcb;                                                    \
                ldsm4(bfr[2 * p][0], bfr[2 * p][1], bfr[2 * p + 1][0], bfr[2 * p + 1][1], \
                      Bst + row * 64 + ((ch ^ ((row >> 1) & 3)) << 4));                   \
            }                                                                             \
            _Pragma("unroll") for (int mf = 0; mf < 4; mf++)                              \
                _Pragma("unroll") for (int nf = 0; nf < 4; nf++)                          \
                    mma16(acc[mf][nf], af[mf][0], af[mf][1], af[mf][2], af[mf][3],        \
                          bfr[nf][0], bfr[nf][1]);                                        \
        }                                                                                 \
    }

#define LOAD_BF(slab, stg)                                                              \
    {                                                                                   \
        int kk0 = (slab)*KSB;                                                           \
        uint32_t* Ad = As + (size_t)(stg)*GW;                                           \
        uint32_t* Bd = Bs + (size_t)(stg)*GW;                                           \
        _Pragma("unroll") for (int p = 0; p < 2; p++) {                                 \
            int c = tid + p * 256;                                                      \
            int r = c >> 2, ch = c & 3;                                                 \
            int sw = ((ch ^ ((r >> 1) & 3)) << 2);                                      \
            cp_async16(Ad + r * KW + sw, Ab + (size_t)(m0 + r) * K + kk0 + ch * 8);     \
            cp_async16(Bd + r * KW + sw, Wp + (size_t)(c0 + r) * K + kk0 + ch * 8);     \
        }                                                                               \
        cp_commit();                                                                    \
    }

// ---------------- bf16 GEMM, row-major output ----------------
__global__ __launch_bounds__(256) void gemm_bf16_row(
    const __nv_bfloat16* __restrict__ A, const __nv_bfloat16* __restrict__ W,
    const float* __restrict__ bias, float* __restrict__ Yf, __nv_bfloat16* __restrict__ Yh,
    int N, int K, int Cout, int mode) {
    extern __shared__ uint32_t smu[];
    uint32_t* As = smu;
    uint32_t* Bs = smu + NSTAGE * GW;
    int b = blockIdx.z;
    int m0 = blockIdx.x * BM;
    int c0 = blockIdx.y * BN;
    int tid = threadIdx.x;
    int warp = tid >> 5, lane = tid & 31;
    int g = lane >> 2, lq = lane & 3;
    int wm = (warp >> 2) * 64;
    int wn = (warp & 3) * 32;
    float acc[4][4][4] = {};
    const __nv_bfloat16* Ab = A + (size_t)b * N * K;
    const __nv_bfloat16* Wp = W;

    GEMM_MAINLOOP(Ab, Wp, K)

#pragma unroll
    for (int mf = 0; mf < 4; mf++) {
#pragma unroll
        for (int nf = 0; nf < 4; nf++) {
            int co = c0 + wn + nf * 8 + lq * 2;
            float b0v = bias[co], b1v = bias[co + 1];
#pragma unroll
            for (int hr = 0; hr < 2; hr++) {
                int m = m0 + wm + mf * 16 + g + hr * 8;
                float v0 = acc[mf][nf][hr * 2 + 0] + b0v;
                float v1 = acc[mf][nf][hr * 2 + 1] + b1v;
                if (mode == 1) {
                    v0 = v0 / (1.f + expf(-v0));
                    v1 = v1 / (1.f + expf(-v1));
                    __nv_bfloat162 hv;
                    hv.x = __float2bfloat16_rn(v0);
                    hv.y = __float2bfloat16_rn(v1);
                    *(__nv_bfloat162*)(Yh + ((size_t)b * N + m) * Cout + co) = hv;
                } else {
                    *(float2*)(Yf + ((size_t)b * N + m) * Cout + co) = make_float2(v0, v1);
                }
            }
        }
    }
}

// ---------------- bf16 GEMM, channel-major fused output (batch-strided W) ----------
__global__ __launch_bounds__(256) void gemm_bf16_cm(
    const __nv_bfloat16* __restrict__ A, const __nv_bfloat16* __restrict__ W,
    const float* __restrict__ bias,
    const float* __restrict__ resid1, const float* __restrict__ resid2,
    const float* __restrict__ scal1, const float* __restrict__ scal2,
    float* __restrict__ out, int N, int K, int Cout, int mode, int wstride) {
    extern __shared__ uint32_t smu[];
    uint32_t* As = smu;
    uint32_t* Bs = smu + NSTAGE * GW;
    int b = blockIdx.z;
    int m0 = blockIdx.x * BM;
    int c0 = blockIdx.y * BN;
    int tid = threadIdx.x;
    int warp = tid >> 5, lane = tid & 31;
    int g = lane >> 2, lq = lane & 3;
    int wm = (warp >> 2) * 64;
    int wn = (warp & 3) * 32;
    float acc[4][4][4] = {};
    const __nv_bfloat16* Ab = A + (size_t)b * N * K;
    const __nv_bfloat16* Wp = W + (size_t)b * wstride;

    GEMM_MAINLOOP(Ab, Wp, K)

#pragma unroll
    for (int nf = 0; nf < 4; nf++) {
#pragma unroll
        for (int cj = 0; cj < 2; cj++) {
            int co = c0 + wn + nf * 8 + lq * 2 + cj;
            float bv = bias[co];
            float s1 = scal1[co];
            float s2 = (mode == 1) ? scal2[co] : 0.f;
#pragma unroll
            for (int mf = 0; mf < 4; mf++) {
#pragma unroll
                for (int hr = 0; hr < 2; hr++) {
                    int m = m0 + wm + mf * 16 + g + hr * 8;
                    size_t idx = ((size_t)b * Cout + co) * (size_t)N + m;
                    float val = acc[mf][nf][hr * 2 + cj] + bv;
                    if (mode == 0)
                        out[idx] = resid1[idx] + val * s1;
                    else
                        out[idx] = resid1[idx] + (resid2[idx] + val * s1) * s2;
                }
            }
        }
    }
}

// ---------------- LayerNorm + elu+1 (in place on (rows, C)) — for k ----------------
__global__ void ln_elu_kernel(float* __restrict__ x, const float* __restrict__ w,
                              const float* __restrict__ bvec) {
    int r = blockIdx.x;
    float* p = x + (size_t)r * Cn;
    int t = threadIdx.x;  // 128
    float v0 = p[t], v1 = p[t + 128], v2 = p[t + 256];
    float s = v0 + v1 + v2;
    float s2 = v0 * v0 + v1 * v1 + v2 * v2;
    __shared__ float red[128];
    red[t] = s;
    __syncthreads();
    for (int st = 64; st > 0; st >>= 1) {
        if (t < st) red[t] += red[t + st];
        __syncthreads();
    }
    float mu = red[0] * (1.f / (float)Cn);
    __syncthreads();
    red[t] = s2;
    __syncthreads();
    for (int st = 64; st > 0; st >>= 1) {
        if (t < st) red[t] += red[t + st];
        __syncthreads();
    }
    float var = red[0] * (1.f / (float)Cn) - mu * mu;
    float inv = rsqrtf(var + LN_EPS);
    float y;
    y = (v0 - mu) * inv * w[t] + bvec[t];
    p[t] = (y > 0.f) ? y + 1.f : expf(y);
    y = (v1 - mu) * inv * w[t + 128] + bvec[t + 128];
    p[t + 128] = (y > 0.f) ? y + 1.f : expf(y);
    y = (v2 - mu) * inv * w[t + 256] + bvec[t + 256];
    p[t + 256] = (y > 0.f) ? y + 1.f : expf(y);
}

// ---------------- q: LayerNorm + elu+1 + den fold -> bf16 q' ----------------
__global__ void ln_elu_q_den(const float* __restrict__ x, const float* __restrict__ ksum,
                             const float* __restrict__ w, const float* __restrict__ bvec,
                             __nv_bfloat16* __restrict__ qp) {
    int r = blockIdx.x;
    int b = r / NQ;
    const float* p = x + (size_t)r * Cn;
    int t = threadIdx.x;  // 128
    float v0 = p[t], v1 = p[t + 128], v2 = p[t + 256];
    float s = v0 + v1 + v2;
    float s2 = v0 * v0 + v1 * v1 + v2 * v2;
    __shared__ float red[128];
    __shared__ float yb[384];
    __shared__ float den[8];
    red[t] = s;
    __syncthreads();
    for (int st = 64; st > 0; st >>= 1) {
        if (t < st) red[t] += red[t + st];
        __syncthreads();
    }
    float mu = red[0] * (1.f / (float)Cn);
    __syncthreads();
    red[t] = s2;
    __syncthreads();
    for (int st = 64; st > 0; st >>= 1) {
        if (t < st) red[t] += red[t + st];
        __syncthreads();
    }
    float var = red[0] * (1.f / (float)Cn) - mu * mu;
    float inv = rsqrtf(var + LN_EPS);
    float y0 = (v0 - mu) * inv * w[t] + bvec[t];
    y0 = (y0 > 0.f) ? y0 + 1.f : expf(y0);
    float y1 = (v1 - mu) * inv * w[t + 128] + bvec[t + 128];
    y1 = (y1 > 0.f) ? y1 + 1.f : expf(y1);
    float y2 = (v2 - mu) * inv * w[t + 256] + bvec[t + 256];
    y2 = (y2 > 0.f) ? y2 + 1.f : expf(y2);
    yb[t] = y0; yb[t + 128] = y1; yb[t + 256] = y2;
    __syncthreads();
    if (t < 8) {
        const float* ksr = ksum + ((size_t)b * Hn + t) * Dn;
        float sd = 0.f;
#pragma unroll
        for (int j = 0; j < Dn; j++) sd += yb[t * Dn + j] * ksr[j];
        den[t] = sd + 1e-8f;
    }
    __syncthreads();
    __nv_bfloat16* o = qp + (size_t)r * Cn;
    o[t] = __float2bfloat16_rn(y0 / den[t / Dn]);
    o[t + 128] = __float2bfloat16_rn(y1 / den[(t + 128) / Dn]);
    o[t + 256] = __float2bfloat16_rn(y2 / den[(t + 256) / Dn]);
}

// ---------------- zero kv/ksum ----------------
__global__ void zero_kv(float* __restrict__ kv, float* __restrict__ ksum) {
    int i = blockIdx.x * 256 + threadIdx.x;
    int nkv = Bn * Hn * Dn * Dn;
    if (i < nkv) kv[i] = 0.f;
    if (i < Bn * Hn * Dn) ksum[i] = 0.f;
}

// ---------------- kv_sum + k_sum v2: register outer-product + NK split --------------
__global__ void kv_v2(const float* __restrict__ k, const float* __restrict__ v,
                      float* __restrict__ kv, float* __restrict__ ksum) {
    int bh = blockIdx.x;
    int chunk = blockIdx.y;
    int b = bh >> 3, h = bh & 7;
    __shared__ float ks[32][49];
    __shared__ float vs[32][49];
    int tid = threadIdx.x;  // 256
    int di = tid >> 4, ei = tid & 15;
    int d0 = di * 3, e0 = ei * 3;
    float acc[3][3] = {};
    float ksa[3] = {};
    int nbeg = chunk * (NK / 4);
    for (int n0 = nbeg; n0 < nbeg + NK / 4; n0 += 32) {
        for (int i = tid; i < 32 * Dn; i += 256) {
            int nn = i / Dn, dd = i % Dn;
            size_t base = ((size_t)b * NK + n0 + nn) * Cn + h * Dn + dd;
            ks[nn][dd] = k[base];
            vs[nn][dd] = v[base];
        }
        __syncthreads();
#pragma unroll 4
        for (int nn = 0; nn < 32; nn++) {
            float kd0 = ks[nn][d0], kd1 = ks[nn][d0 + 1], kd2 = ks[nn][d0 + 2];
            float ve0 = vs[nn][e0], ve1 = vs[nn][e0 + 1], ve2 = vs[nn][e0 + 2];
            acc[0][0] += kd0 * ve0; acc[0][1] += kd0 * ve1; acc[0][2] += kd0 * ve2;
            acc[1][0] += kd1 * ve0; acc[1][1] += kd1 * ve1; acc[1][2] += kd1 * ve2;
            acc[2][0] += kd2 * ve0; acc[2][1] += kd2 * ve1; acc[2][2] += kd2 * ve2;
            if (ei == 0) { ksa[0] += kd0; ksa[1] += kd1; ksa[2] += kd2; }
        }
        __syncthreads();
    }
    float* kvb = kv + (size_t)bh * Dn * Dn;
#pragma unroll
    for (int i = 0; i < 3; i++)
#pragma unroll
        for (int j = 0; j < 3; j++)
            atomicAdd(&kvb[(d0 + i) * Dn + e0 + j], acc[i][j]);
    if (ei == 0)
#pragma unroll
        for (int i = 0; i < 3; i++) atomicAdd(&ksum[bh * Dn + d0 + i], ksa[i]);
}

// ---------------- make_M: Wt[b][co][h*48+d] = sum_e kv[b,h,d,e] * Wo[co,h*48+e] ------
__global__ void make_M(const float* __restrict__ kv, const float* __restrict__ Wo,
                       __nv_bfloat16* __restrict__ Wt) {
    int cb = blockIdx.x;  // 0..2 (co block of 128)
    int h = blockIdx.y;
    int b = blockIdx.z;
    __shared__ float kvs[Dn][49];
    __shared__ float wos[Dn][132];  // [e][co]
    int tid = threadIdx.x;  // 256
    for (int i = tid; i < Dn * Dn; i += 256)
        kvs[i / Dn][i % Dn] = kv[((size_t)b * Hn + h) * Dn * Dn + i];
    for (int i = tid; i < 128 * Dn; i += 256) {
        int co = i / Dn, e = i % Dn;
        wos[e][co] = Wo[(size_t)(cb * 128 + co) * Cn + h * Dn + e];
    }
    __syncthreads();
    int cog = tid & 15, dg = tid >> 4;
    int co0 = cog * 8, d0 = dg * 3;
    float acc[8][3] = {};
#pragma unroll 4
    for (int e = 0; e < Dn; e++) {
        float kd0 = kvs[d0][e], kd1 = kvs[d0 + 1][e], kd2 = kvs[d0 + 2][e];
#pragma unroll
        for (int i = 0; i < 8; i++) {
            float wv = wos[e][co0 + i];
            acc[i][0] += wv * kd0;
            acc[i][1] += wv * kd1;
            acc[i][2] += wv * kd2;
        }
    }
#pragma unroll
    for (int i = 0; i < 8; i++)
#pragma unroll
        for (int j = 0; j < 3; j++)
            Wt[((size_t)b * Cn + cb * 128 + co0 + i) * Cn + h * Dn + d0 + j] =
                __float2bfloat16_rn(acc[i][j]);
}

// ---------------- host launch ----------------
extern "C" void kernel_launch(void* const* d_in, const int* in_sizes, int n_in,
                              void* d_out, int out_size) {
    const float* query = (const float*)d_in[0];
    const float* key = (const float*)d_in[1];
    const float* value = (const float*)d_in[2];
    const float* ada_gamma = (const float*)d_in[3];
    const float* ada_beta = (const float*)d_in[4];
    const float* Wq = (const float*)d_in[5];
    const float* bq = (const float*)d_in[6];
    const float* Wk = (const float*)d_in[7];
    const float* bk = (const float*)d_in[8];
    const float* Wv = (const float*)d_in[9];
    const float* bv = (const float*)d_in[10];
    const float* Wo = (const float*)d_in[11];
    const float* bo = (const float*)d_in[12];
    const float* lnq_w = (const float*)d_in[13];
    const float* lnq_b = (const float*)d_in[14];
    const float* lnk_w = (const float*)d_in[15];
    const float* lnk_b = (const float*)d_in[16];
    const float* attn_scalar = (const float*)d_in[17];
    const float* ffn_gamma = (const float*)d_in[18];
    const float* ffn_beta = (const float*)d_in[19];
    const float* W1 = (const float*)d_in[20];
    const float* b1 = (const float*)d_in[21];
    const float* W2 = (const float*)d_in[22];
    const float* b2 = (const float*)d_in[23];
    const float* ffn_scalar = (const float*)d_in[24];
    const float* final_scalar = (const float*)d_in[25];
    float* out = (float*)d_out;

    float *q, *k, *v, *working, *kv, *ksum, *gx, *meanc;
    __nv_bfloat16 *ada_b, *key_b, *val_b, *qp_b, *nrm_b, *h_b, *wts, *M_b;
    cudaGetSymbolAddress((void**)&q, g_q);
    cudaGetSymbolAddress((void**)&k, g_k);
    cudaGetSymbolAddress((void**)&v, g_v);
    cudaGetSymbolAddress((void**)&working, g_working);
    cudaGetSymbolAddress((void**)&kv, g_kv);
    cudaGetSymbolAddress((void**)&ksum, g_ksum);
    cudaGetSymbolAddress((void**)&gx, g_gx);
    cudaGetSymbolAddress((void**)&meanc, g_meanc);
    cudaGetSymbolAddress((void**)&ada_b, b_ada);
    cudaGetSymbolAddress((void**)&key_b, b_key);
    cudaGetSymbolAddress((void**)&val_b, b_val);
    cudaGetSymbolAddress((void**)&qp_b, b_qp);
    cudaGetSymbolAddress((void**)&nrm_b, b_nrm);
    cudaGetSymbolAddress((void**)&h_b, b_h);
    cudaGetSymbolAddress((void**)&wts, b_wts);
    cudaGetSymbolAddress((void**)&M_b, b_M);

    __nv_bfloat16* wq_b = wts;
    __nv_bfloat16* wk_b = wts + CC;
    __nv_bfloat16* wv_b = wts + 2 * CC;
    __nv_bfloat16* w1_b = wts + 4 * CC;
    __nv_bfloat16* w2_b = wts + 4 * CC + FC;

    cudaFuncSetAttribute(gemm_bf16_row, cudaFuncAttributeMaxDynamicSharedMemorySize, GEMM_SMEM);
    cudaFuncSetAttribute(gemm_bf16_cm, cudaFuncAttributeMaxDynamicSharedMemorySize, GEMM_SMEM);

    // 0) all weight conversions (wo_b slot converted but unused; harmless)
    conv_f2bf_all<<<1728, 256>>>((const float4*)Wq, (const float4*)Wk, (const float4*)Wv,
                                 (const float4*)Wo, (const float4*)W1, (const float4*)W2,
                                 (__nv_bfloat162*)wts);

    // 0b) key/value transpose-convert to bf16 rows
    transconv_kernel<<<dim3(Cn / 64, NK / 32, Bn), 256>>>(key, key_b, nullptr, nullptr,
                                                          nullptr, nullptr, NK, 0);
    transconv_kernel<<<dim3(Cn / 64, NK / 32, Bn), 256>>>(value, val_b, nullptr, nullptr,
                                                          nullptr, nullptr, NK, 0);

    // 1) GRN on query -> ada (bf16 rows, fused transpose)
    grn_reduce_kernel<<<Bn * Cn, 256>>>(query, gx, NQ);
    grn_mean_kernel<<<Bn, 128>>>(gx, meanc);
    transconv_kernel<<<dim3(Cn / 64, NQ / 32, Bn), 256>>>(query, ada_b, gx, meanc,
                                                          ada_gamma, ada_beta, NQ, 1);

    // 2) projections
    gemm_bf16_row<<<dim3(NQ / BM, Cn / BN, Bn), 256, GEMM_SMEM>>>(ada_b, wq_b, bq, q, nullptr,
                                                                  NQ, Cn, Cn, 0);
    gemm_bf16_row<<<dim3(NK / BM, Cn / BN, Bn), 256, GEMM_SMEM>>>(key_b, wk_b, bk, k, nullptr,
                                                                  NK, Cn, Cn, 0);
    gemm_bf16_row<<<dim3(NK / BM, Cn / BN, Bn), 256, GEMM_SMEM>>>(val_b, wv_b, bv, v, nullptr,
                                                                  NK, Cn, Cn, 0);

    // 3) LN + elu+1 on k (in place, fp32)
    ln_elu_kernel<<<Bn * NK, 128>>>(k, lnk_w, lnk_b);

    // 4) kv_sum, k_sum (zero + split accumulate)
    zero_kv<<<(Bn * Hn * Dn * Dn + 255) / 256, 256>>>(kv, ksum);
    kv_v2<<<dim3(Bn * Hn, 4), 256>>>(k, v, kv, ksum);

    // 5a) q: LN + elu+1 + fold den -> bf16 q'
    ln_elu_q_den<<<Bn * NQ, 128>>>(q, ksum, lnq_w, lnq_b, qp_b);

    // 5b) fold kv into Wo: per-batch effective weight M
    make_M<<<dim3(Cn / 128, Hn, Bn), 256>>>(kv, Wo, M_b);

    // 6) (attention + Wo) as ONE GEMM: working = query + (q' @ M^T + bo) * attn_scalar
    gemm_bf16_cm<<<dim3(NQ / BM, Cn / BN, Bn), 256, GEMM_SMEM>>>(
        qp_b, M_b, bo, query, nullptr, attn_scalar, nullptr, working, NQ, Cn, Cn, 0,
        Cn * Cn);

    // 7) GRN on working -> normed (bf16 rows, fused transpose)
    grn_reduce_kernel<<<Bn * Cn, 256>>>(working, gx, NQ);
    grn_mean_kernel<<<Bn, 128>>>(gx, meanc);
    transconv_kernel<<<dim3(Cn / 64, NQ / 32, Bn), 256>>>(working, nrm_b, gx, meanc,
                                                          ffn_gamma, ffn_beta, NQ, 1);

    // 8) FFN1 (+silu) -> h (bf16 rows)
    gemm_bf16_row<<<dim3(NQ / BM, Fn / BN, Bn), 256, GEMM_SMEM>>>(nrm_b, w1_b, b1, nullptr, h_b,
                                                                  NQ, Cn, Fn, 1);

    // 9) FFN2 + ffn residual + final residual -> out (fp32, channel-major)
    gemm_bf16_cm<<<dim3(NQ / BM, Cn / BN, Bn), 256, GEMM_SMEM>>>(
        h_b, w2_b, b2, query, working, ffn_scalar, final_scalar, out, NQ, Fn, Cn, 1, 0);
}